// round 9
// baseline (speedup 1.0000x reference)
#include <cuda_runtime.h>
#include <math.h>

#define NN 8192
#define DD 32
#define HH 128
#define MMQ 8
#define TPB 1024
#define NBLK 128
#define SPW 2
#define P36 36
#define P132 132
#define NSTEPS 10

// ---------------- device state ----------------
__device__ float g_yz[NN * DD];
__device__ float g_ylp[NN];
__device__ float g_y1z[NN * DD];
__device__ float g_y1lp[NN];
__device__ float g_kz[6][NN * DD];
__device__ float g_klp[6][NN];
__device__ float g_IPT[DD * DD];    // IPT[j*32+k] = IP[k][j]
__device__ float g_MmatT[HH * HH];  // MmatT[j*128+i] = W2[j,i]*B[i,j]
__device__ float g_trP;
__device__ float g_t, g_dt, g_dtc, g_t1;
__device__ int g_done, g_accept;
__device__ float g_partial[NBLK];

// RK45 combine/error coefficients
#define C1f ((float)(35.0 / 384.0))
#define C3f ((float)(500.0 / 1113.0))
#define C4f ((float)(125.0 / 192.0))
#define C5f ((float)(-2187.0 / 6784.0))
#define C6f ((float)(11.0 / 84.0))
#define E1f ((float)(35.0 / 384.0 - 5179.0 / 57600.0))
#define E3f ((float)(500.0 / 1113.0 - 7571.0 / 16695.0))
#define E4f ((float)(125.0 / 192.0 - 393.0 / 640.0))
#define E5f ((float)(-2187.0 / 6784.0 + 92097.0 / 339200.0))
#define E6f ((float)(11.0 / 84.0 - 187.0 / 2100.0))
#define E7f ((float)(-1.0 / 40.0))

// ---------------- prep: projection + M matrix ----------------
__global__ void prep_kernel(const float* __restrict__ G, const float* __restrict__ W1,
                            const float* __restrict__ W2, const float* __restrict__ W3,
                            const float* __restrict__ T) {
    __shared__ double Ad[MMQ][MMQ];
    __shared__ double Ainv[MMQ][MMQ];
    __shared__ float sAinvG[MMQ][DD];
    __shared__ float sP[DD][DD];
    __shared__ float sC[DD][HH];
    int tid = threadIdx.x;

    if (tid < MMQ * MMQ) {
        int i = tid >> 3, j = tid & 7;
        double s = 0.0;
        for (int d = 0; d < DD; d++) s += (double)G[i * DD + d] * (double)G[j * DD + d];
        Ad[i][j] = s;
    }
    __syncthreads();
    if (tid == 0) {
        double Mx[MMQ][2 * MMQ];
        for (int i = 0; i < MMQ; i++)
            for (int j = 0; j < MMQ; j++) {
                Mx[i][j] = Ad[i][j];
                Mx[i][MMQ + j] = (i == j) ? 1.0 : 0.0;
            }
        for (int col = 0; col < MMQ; col++) {
            int piv = col;
            double best = fabs(Mx[col][col]);
            for (int r = col + 1; r < MMQ; r++) {
                double v = fabs(Mx[r][col]);
                if (v > best) { best = v; piv = r; }
            }
            if (piv != col)
                for (int j = 0; j < 2 * MMQ; j++) {
                    double tmp = Mx[col][j]; Mx[col][j] = Mx[piv][j]; Mx[piv][j] = tmp;
                }
            double inv = 1.0 / Mx[col][col];
            for (int j = 0; j < 2 * MMQ; j++) Mx[col][j] *= inv;
            for (int r = 0; r < MMQ; r++)
                if (r != col) {
                    double fv = Mx[r][col];
                    for (int j = 0; j < 2 * MMQ; j++) Mx[r][j] -= fv * Mx[col][j];
                }
        }
        for (int i = 0; i < MMQ; i++)
            for (int j = 0; j < MMQ; j++) Ainv[i][j] = Mx[i][MMQ + j];
    }
    __syncthreads();
    if (tid < MMQ * DD) {
        int m = tid >> 5, d = tid & 31;
        double s = 0.0;
        for (int k = 0; k < MMQ; k++) s += Ainv[m][k] * (double)G[k * DD + d];
        sAinvG[m][d] = (float)s;
    }
    __syncthreads();
    for (int e = tid; e < DD * DD; e += blockDim.x) {
        int a = e >> 5, b = e & 31;
        float s = 0.f;
        for (int m = 0; m < MMQ; m++) s += G[m * DD + a] * sAinvG[m][b];
        sP[a][b] = s;
        g_IPT[b * DD + a] = ((a == b) ? 1.0f : 0.0f) - s;  // IP[a][b] stored transposed
    }
    __syncthreads();
    if (tid == 0) {
        float tr = 0.f;
        for (int a = 0; a < DD; a++) tr += sP[a][a];
        g_trP = tr;
        float t1 = 2.0f * T[0];
        g_t = 0.f;
        g_dt = 0.25f;
        g_t1 = t1;
        g_accept = 0;
        int done = (0.f >= t1 - 1e-9f) ? 1 : 0;
        g_done = done;
        g_dtc = done ? 0.001f : fminf(0.25f, t1);
    }
    // C = IP @ W3  (32 x 128)
    for (int e = tid; e < DD * HH; e += blockDim.x) {
        int a = e >> 7, j = e & 127;
        float s = 0.f;
        for (int b = 0; b < DD; b++)
            s += (((a == b) ? 1.0f : 0.0f) - sP[a][b]) * W3[b * HH + j];
        sC[a][j] = s;
    }
    __syncthreads();
    // MmatT[j][i] = W2[j,i] * B[i,j],  B = W1 @ C
    for (int e = tid; e < HH * HH; e += blockDim.x) {
        int j = e >> 7, i = e & 127;
        float s = 0.f;
        for (int a = 0; a < DD; a++) s += W1[i * DD + a] * sC[a][j];
        g_MmatT[j * HH + i] = s * W2[j * HH + i];
    }
}

// ---------------- init ----------------
__global__ void init_kernel(const float* __restrict__ z) {
    int total = NN * DD + NN;
    for (int i = blockIdx.x * blockDim.x + threadIdx.x; i < total; i += gridDim.x * blockDim.x) {
        if (i < NN * DD) g_yz[i] = z[i];
        else g_ylp[i - NN * DD] = 0.f;
    }
}

// ---------------- the f(y) stage kernel ----------------
// mode 0: normal stage (x = y + dtc*sum a_j k_j), store k[stage]
// mode 1: first stage of a step: apply previous accept (select), x = y, store k[0]
// mode 2: k7 stage: compute y1 in-kernel from k1..k6, x = y1, do NOT store k7;
//         accumulate error-norm partials instead.
struct Coefs {
    float a0, a1, a2, a3, a4;
    int nk;
    int stage;
    int mode;
};

__global__ __launch_bounds__(TPB, 1) void stage_kernel(
    const float* __restrict__ W1, const float* __restrict__ b1,
    const float* __restrict__ W2, const float* __restrict__ b2,
    const float* __restrict__ W3, const float* __restrict__ b3, Coefs cf) {
    extern __shared__ float sm[];
    float* sW1 = sm;                        // HH*P36
    float* sW2 = sW1 + HH * P36;            // HH*P132
    float* sMT = sW2 + HH * P132;           // HH*P132
    float* sW3 = sMT + HH * P132;           // DD*P132
    float* sIPT = sW3 + DD * P132;          // DD*P36
    float* sb1 = sIPT + DD * P36;           // HH
    float* sb2 = sb1 + HH;                  // HH
    float* sb3 = sb2 + HH;                  // DD
    float* sred = sb3 + DD;                 // 32 (err reduction)
    float* xs = sred + 32;                  // 32*SPW*DD
    float* hs = xs + 32 * SPW * DD;         // 32*SPW*HH

    int tid = threadIdx.x;
    int w = tid >> 5, lane = tid & 31;
    int n0 = (blockIdx.x * (TPB / 32) + w) * SPW;
    float dtc = g_dtc;
    float* xw = xs + w * (SPW * DD);
    float* hw = hs + w * (SPW * HH);

    // ---- stage input x (global loads issued first; latency hides under staging)
    float xv[SPW];
    if (cf.mode == 1) {
        int accept = g_accept;
#pragma unroll
        for (int s = 0; s < SPW; s++) {
            int nd = (n0 + s) * DD + lane;
            float v = accept ? g_y1z[nd] : g_yz[nd];
            if (accept) g_yz[nd] = v;
            xv[s] = v;
            xw[s * DD + lane] = v;
        }
        if (lane < SPW && accept) {
            int n = n0 + lane;
            g_ylp[n] = g_y1lp[n];
        }
    } else if (cf.mode == 2) {
#pragma unroll
        for (int s = 0; s < SPW; s++) {
            int nd = (n0 + s) * DD + lane;
            float yv = g_yz[nd];
            float acc = C1f * g_kz[0][nd] + C3f * g_kz[2][nd] + C4f * g_kz[3][nd] +
                        C5f * g_kz[4][nd] + C6f * g_kz[5][nd];
            float y1 = yv + dtc * acc;
            g_y1z[nd] = y1;
            xv[s] = y1;
            xw[s * DD + lane] = y1;
        }
    } else {
#pragma unroll
        for (int s = 0; s < SPW; s++) {
            int nd = (n0 + s) * DD + lane;
            float v = g_yz[nd];
            float acc = cf.a0 * g_kz[0][nd];
            if (cf.nk > 1) acc += cf.a1 * g_kz[1][nd];
            if (cf.nk > 2) acc += cf.a2 * g_kz[2][nd];
            if (cf.nk > 3) acc += cf.a3 * g_kz[3][nd];
            if (cf.nk > 4) acc += cf.a4 * g_kz[4][nd];
            v += dtc * acc;
            xv[s] = v;
            xw[s * DD + lane] = v;
        }
    }

    // ---- weight staging
    for (int e = tid; e < HH * DD; e += TPB) sW1[(e >> 5) * P36 + (e & 31)] = W1[e];
    for (int e = tid; e < HH * HH; e += TPB) sW2[(e >> 7) * P132 + (e & 127)] = W2[e];
    for (int e = tid; e < HH * HH; e += TPB) sMT[(e >> 7) * P132 + (e & 127)] = g_MmatT[e];
    for (int e = tid; e < DD * HH; e += TPB) sW3[(e >> 7) * P132 + (e & 127)] = W3[e];
    for (int e = tid; e < DD * DD; e += TPB) sIPT[(e >> 5) * P36 + (e & 31)] = g_IPT[e];
    if (tid < HH) { sb1[tid] = b1[tid]; sb2[tid] = b2[tid]; }
    if (tid < DD) sb3[tid] = b3[tid];
    __syncthreads();

    // pass 1: h1pre = W1 @ x + b1 (lane owns j = c*32+lane)
    float h1[SPW][4];
#pragma unroll
    for (int s = 0; s < SPW; s++)
#pragma unroll
        for (int c = 0; c < 4; c++) h1[s][c] = sb1[c * 32 + lane];
#pragma unroll
    for (int d0 = 0; d0 < DD; d0 += 4) {
        float4 x4[SPW];
#pragma unroll
        for (int s = 0; s < SPW; s++) x4[s] = *(const float4*)&xw[s * DD + d0];
#pragma unroll
        for (int c = 0; c < 4; c++) {
            float4 wv = *(const float4*)&sW1[(c * 32 + lane) * P36 + d0];
#pragma unroll
            for (int s = 0; s < SPW; s++)
                h1[s][c] += wv.x * x4[s].x + wv.y * x4[s].y + wv.z * x4[s].z + wv.w * x4[s].w;
        }
    }
#pragma unroll
    for (int s = 0; s < SPW; s++)
#pragma unroll
        for (int c = 0; c < 4; c++) hw[s * HH + c * 32 + lane] = fmaxf(h1[s][c], 0.f);
    __syncwarp();

    // pass 2: h2pre = W2 @ relu(h1) + b2, and v[j] = sum_i MT[j][i]*mask(h1[i])
    float h2[SPW][4], vv[SPW][4];
#pragma unroll
    for (int s = 0; s < SPW; s++)
#pragma unroll
        for (int c = 0; c < 4; c++) {
            h2[s][c] = sb2[c * 32 + lane];
            vv[s][c] = 0.f;
        }
    for (int i0 = 0; i0 < HH; i0 += 4) {
        float4 h4[SPW], m4[SPW];
#pragma unroll
        for (int s = 0; s < SPW; s++) {
            h4[s] = *(const float4*)&hw[s * HH + i0];
            m4[s].x = h4[s].x > 0.f ? 1.f : 0.f;
            m4[s].y = h4[s].y > 0.f ? 1.f : 0.f;
            m4[s].z = h4[s].z > 0.f ? 1.f : 0.f;
            m4[s].w = h4[s].w > 0.f ? 1.f : 0.f;
        }
#pragma unroll
        for (int c = 0; c < 4; c++) {
            int j = c * 32 + lane;
            float4 w2 = *(const float4*)&sW2[j * P132 + i0];
            float4 mm = *(const float4*)&sMT[j * P132 + i0];
#pragma unroll
            for (int s = 0; s < SPW; s++) {
                h2[s][c] += w2.x * h4[s].x + w2.y * h4[s].y + w2.z * h4[s].z + w2.w * h4[s].w;
                vv[s][c] += mm.x * m4[s].x + mm.y * m4[s].y + mm.z * m4[s].z + mm.w * m4[s].w;
            }
        }
    }
    __syncwarp();
    // relu(h2) back to staging; dlogp partial = sum_j d2[j]*v[j]
    float dlp[SPW];
#pragma unroll
    for (int s = 0; s < SPW; s++) {
        float acc = 0.f;
#pragma unroll
        for (int c = 0; c < 4; c++) {
            float h2v = h2[s][c];
            hw[s * HH + c * 32 + lane] = fmaxf(h2v, 0.f);
            if (h2v > 0.f) acc += vv[s][c];
        }
        dlp[s] = acc;
    }
    __syncwarp();

    // pass 3: dF = W3 @ relu(h2) + b3 (lane owns d = lane)
    float dF[SPW];
#pragma unroll
    for (int s = 0; s < SPW; s++) dF[s] = sb3[lane];
    for (int h0 = 0; h0 < HH; h0 += 4) {
        float4 w3 = *(const float4*)&sW3[lane * P132 + h0];
#pragma unroll
        for (int s = 0; s < SPW; s++) {
            float4 h24 = *(const float4*)&hw[s * HH + h0];
            dF[s] += w3.x * h24.x + w3.y * h24.y + w3.z * h24.z + w3.w * h24.w;
        }
    }
    __syncwarp();
    // t = x - dF -> staging (first 32 slots of hw row)
#pragma unroll
    for (int s = 0; s < SPW; s++) hw[s * HH + lane] = xv[s] - dF[s];
    __syncwarp();

    // pass 4: dz = (x - dF) @ IP - x
    float dz[SPW];
#pragma unroll
    for (int s = 0; s < SPW; s++) dz[s] = -xv[s];
#pragma unroll
    for (int k0 = 0; k0 < DD; k0 += 4) {
        float4 ip = *(const float4*)&sIPT[lane * P36 + k0];
#pragma unroll
        for (int s = 0; s < SPW; s++) {
            float4 t4 = *(const float4*)&hw[s * HH + k0];
            dz[s] += ip.x * t4.x + ip.y * t4.y + ip.z * t4.z + ip.w * t4.w;
        }
    }

    // ---- epilogue
    float trP = g_trP;
    float dlpAll[SPW];
#pragma unroll
    for (int s = 0; s < SPW; s++) {
        float v = dlp[s];
#pragma unroll
        for (int off = 16; off > 0; off >>= 1) v += __shfl_xor_sync(0xffffffffu, v, off);
        dlpAll[s] = v + trP;  // k_lp for this stage
    }

    if (cf.mode != 2) {
#pragma unroll
        for (int s = 0; s < SPW; s++) {
            int n = n0 + s;
            g_kz[cf.stage][n * DD + lane] = dz[s];
            if (lane == 0) g_klp[cf.stage][n] = dlpAll[s];
        }
    } else {
        // error-norm partial accumulation (dz[] is k7z; dlpAll[] is k7lp)
        float acc = 0.f;
#pragma unroll
        for (int s = 0; s < SPW; s++) {
            int nd = (n0 + s) * DD + lane;
            float yv = g_yz[nd];
            float ev = dtc * (E1f * g_kz[0][nd] + E3f * g_kz[2][nd] + E4f * g_kz[3][nd] +
                              E5f * g_kz[4][nd] + E6f * g_kz[5][nd] + E7f * dz[s]);
            float tol = 1e-5f + 1e-5f * fmaxf(fabsf(yv), fabsf(xv[s]));
            float r = ev / tol;
            acc += r * r;
        }
        if (lane < SPW) {
            int s = lane;
            int n = n0 + s;
            float k0l = g_klp[0][n], k2l = g_klp[2][n], k3l = g_klp[3][n],
                  k4l = g_klp[4][n], k5l = g_klp[5][n];
            float ylp = g_ylp[n];
            float y1lp = ylp + dtc * (C1f * k0l + C3f * k2l + C4f * k3l + C5f * k4l + C6f * k5l);
            g_y1lp[n] = y1lp;
            float ev = dtc * (E1f * k0l + E3f * k2l + E4f * k3l + E5f * k4l + E6f * k5l +
                              E7f * dlpAll[s]);
            float tol = 1e-5f + 1e-5f * fmaxf(fabsf(ylp), fabsf(y1lp));
            float r = ev / tol;
            acc += r * r;
        }
        // warp reduce, then block reduce over 32 warps
#pragma unroll
        for (int off = 16; off > 0; off >>= 1) acc += __shfl_xor_sync(0xffffffffu, acc, off);
        if (lane == 0) sred[w] = acc;
        __syncthreads();
        if (w == 0) {
            float v = sred[lane];
#pragma unroll
            for (int off = 16; off > 0; off >>= 1) v += __shfl_xor_sync(0xffffffffu, v, off);
            if (lane == 0) g_partial[blockIdx.x] = v;
        }
    }
}

// ---------------- end step: reduce + controller update + next-step begin ----------------
__global__ void end_kernel() {
    __shared__ float red[NBLK];
    red[threadIdx.x] = g_partial[threadIdx.x];
    __syncthreads();
    for (int s2 = NBLK / 2; s2 > 0; s2 >>= 1) {
        if (threadIdx.x < s2) red[threadIdx.x] += red[threadIdx.x + s2];
        __syncthreads();
    }
    if (threadIdx.x == 0) {
        float errn = sqrtf(red[0] / (float)(NN * (DD + 1)));
        int done = g_done;
        float dtc = g_dtc;
        float t1 = g_t1;
        int accept = (!done) && (errn <= 1.0f);
        g_accept = accept;
        float t = g_t;
        if (accept) t += dtc;
        g_t = t;
        float factor = (errn > 0.f) ? 0.9f * powf(errn, -0.2f) : 10.0f;
        factor = fminf(fmaxf(factor, 0.2f), 10.0f);
        float dt = g_dt;
        if (!done) dt = fminf(fmaxf(dtc * factor, 1e-6f), t1);
        g_dt = dt;
        // fused "begin" for the next step
        int done2 = (t >= t1 - 1e-9f) ? 1 : 0;
        g_done = done2;
        g_dtc = done2 ? 0.001f : fminf(dt, t1 - t);
    }
}

// ---------------- output (applies final pending accept) ----------------
__global__ void final_kernel(float* __restrict__ out) {
    const float* src = g_accept ? g_y1z : g_yz;
    for (int i = blockIdx.x * blockDim.x + threadIdx.x; i < NN * DD; i += gridDim.x * blockDim.x)
        out[i] = src[i];
}

// ---------------- launch ----------------
extern "C" void kernel_launch(void* const* d_in, const int* in_sizes, int n_in,
                              void* d_out, int out_size) {
    const float* z  = (const float*)d_in[0];
    const float* G  = (const float*)d_in[1];
    const float* W1 = (const float*)d_in[2];
    const float* b1 = (const float*)d_in[3];
    const float* W2 = (const float*)d_in[4];
    const float* b2 = (const float*)d_in[5];
    const float* W3 = (const float*)d_in[6];
    const float* b3 = (const float*)d_in[7];
    const float* T  = (const float*)d_in[8];

    const int smem_floats = HH * P36 + 2 * HH * P132 + DD * P132 + DD * P36 +
                            2 * HH + DD + 32 + 32 * SPW * DD + 32 * SPW * HH;
    const int smem_bytes = smem_floats * 4;
    cudaFuncSetAttribute(stage_kernel, cudaFuncAttributeMaxDynamicSharedMemorySize, smem_bytes);

    prep_kernel<<<1, 256>>>(G, W1, W2, W3, T);
    init_kernel<<<256, 256>>>(z);

    Coefs cfs[7];
    cfs[0] = {0.f, 0.f, 0.f, 0.f, 0.f, 0, 0, 1};
    cfs[1] = {0.2f, 0.f, 0.f, 0.f, 0.f, 1, 1, 0};
    cfs[2] = {(float)(3.0 / 40.0), (float)(9.0 / 40.0), 0.f, 0.f, 0.f, 2, 2, 0};
    cfs[3] = {(float)(44.0 / 45.0), (float)(-56.0 / 15.0), (float)(32.0 / 9.0), 0.f, 0.f, 3, 3, 0};
    cfs[4] = {(float)(19372.0 / 6561.0), (float)(-25360.0 / 2187.0), (float)(64448.0 / 6561.0),
              (float)(-212.0 / 729.0), 0.f, 4, 4, 0};
    cfs[5] = {(float)(9017.0 / 3168.0), (float)(-355.0 / 33.0), (float)(46732.0 / 5247.0),
              (float)(49.0 / 176.0), (float)(-5103.0 / 18656.0), 5, 5, 0};
    cfs[6] = {0.f, 0.f, 0.f, 0.f, 0.f, 0, 6, 2};

    for (int step = 0; step < NSTEPS; step++) {
        for (int s = 0; s < 7; s++)
            stage_kernel<<<NBLK, TPB, smem_bytes>>>(W1, b1, W2, b2, W3, b3, cfs[s]);
        end_kernel<<<1, NBLK>>>();
    }
    final_kernel<<<256, 256>>>((float*)d_out);
}

// round 10
// speedup vs baseline: 1.5407x; 1.5407x over previous
#include <cuda_runtime.h>
#include <math.h>

#define NN 8192
#define DD 32
#define HH 128
#define MMQ 8
#define TPB 512
#define NBLK 128
#define SPW 4
#define P36 36
#define P132 132
#define NSTEPS 10

// ---------------- device state ----------------
__device__ float g_yz[NN * DD];
__device__ float g_ylp[NN];
__device__ float g_y1z[NN * DD];
__device__ float g_y1lp[NN];
__device__ float g_kz[6][NN * DD];
__device__ float g_klp[6][NN];
__device__ float g_IPT[DD * DD];    // IPT[j*32+k] = IP[k][j]
__device__ float g_MmatT[HH * HH];  // MmatT[j*128+i] = W2[j,i]*B[i,j]
__device__ float g_trP;
__device__ float g_t1v;
__device__ float g_partial[2][NBLK];
__device__ unsigned g_count;
__device__ volatile unsigned g_gen;

// RK45 combine/error coefficients
#define C1f ((float)(35.0 / 384.0))
#define C3f ((float)(500.0 / 1113.0))
#define C4f ((float)(125.0 / 192.0))
#define C5f ((float)(-2187.0 / 6784.0))
#define C6f ((float)(11.0 / 84.0))
#define E1f ((float)(35.0 / 384.0 - 5179.0 / 57600.0))
#define E3f ((float)(500.0 / 1113.0 - 7571.0 / 16695.0))
#define E4f ((float)(125.0 / 192.0 - 393.0 / 640.0))
#define E5f ((float)(-2187.0 / 6784.0 + 92097.0 / 339200.0))
#define E6f ((float)(11.0 / 84.0 - 187.0 / 2100.0))
#define E7f ((float)(-1.0 / 40.0))

__constant__ float A_TAB[7][5] = {
    {0.f, 0.f, 0.f, 0.f, 0.f},
    {0.2f, 0.f, 0.f, 0.f, 0.f},
    {(float)(3.0 / 40.0), (float)(9.0 / 40.0), 0.f, 0.f, 0.f},
    {(float)(44.0 / 45.0), (float)(-56.0 / 15.0), (float)(32.0 / 9.0), 0.f, 0.f},
    {(float)(19372.0 / 6561.0), (float)(-25360.0 / 2187.0), (float)(64448.0 / 6561.0),
     (float)(-212.0 / 729.0), 0.f},
    {(float)(9017.0 / 3168.0), (float)(-355.0 / 33.0), (float)(46732.0 / 5247.0),
     (float)(49.0 / 176.0), (float)(-5103.0 / 18656.0)},
    {0.f, 0.f, 0.f, 0.f, 0.f}};
__constant__ int NK_TAB[7] = {0, 1, 2, 3, 4, 5, 0};

// ---------------- prep: projection + M matrix ----------------
__global__ void prep_kernel(const float* __restrict__ G, const float* __restrict__ W1,
                            const float* __restrict__ W2, const float* __restrict__ W3,
                            const float* __restrict__ T) {
    __shared__ double Ad[MMQ][MMQ];
    __shared__ double Ainv[MMQ][MMQ];
    __shared__ float sAinvG[MMQ][DD];
    __shared__ float sP[DD][DD];
    __shared__ float sC[DD][HH];
    int tid = threadIdx.x;

    if (tid < MMQ * MMQ) {
        int i = tid >> 3, j = tid & 7;
        double s = 0.0;
        for (int d = 0; d < DD; d++) s += (double)G[i * DD + d] * (double)G[j * DD + d];
        Ad[i][j] = s;
    }
    __syncthreads();
    if (tid == 0) {
        double Mx[MMQ][2 * MMQ];
        for (int i = 0; i < MMQ; i++)
            for (int j = 0; j < MMQ; j++) {
                Mx[i][j] = Ad[i][j];
                Mx[i][MMQ + j] = (i == j) ? 1.0 : 0.0;
            }
        for (int col = 0; col < MMQ; col++) {
            int piv = col;
            double best = fabs(Mx[col][col]);
            for (int r = col + 1; r < MMQ; r++) {
                double v = fabs(Mx[r][col]);
                if (v > best) { best = v; piv = r; }
            }
            if (piv != col)
                for (int j = 0; j < 2 * MMQ; j++) {
                    double tmp = Mx[col][j]; Mx[col][j] = Mx[piv][j]; Mx[piv][j] = tmp;
                }
            double inv = 1.0 / Mx[col][col];
            for (int j = 0; j < 2 * MMQ; j++) Mx[col][j] *= inv;
            for (int r = 0; r < MMQ; r++)
                if (r != col) {
                    double fv = Mx[r][col];
                    for (int j = 0; j < 2 * MMQ; j++) Mx[r][j] -= fv * Mx[col][j];
                }
        }
        for (int i = 0; i < MMQ; i++)
            for (int j = 0; j < MMQ; j++) Ainv[i][j] = Mx[i][MMQ + j];
    }
    __syncthreads();
    if (tid < MMQ * DD) {
        int m = tid >> 5, d = tid & 31;
        double s = 0.0;
        for (int k = 0; k < MMQ; k++) s += Ainv[m][k] * (double)G[k * DD + d];
        sAinvG[m][d] = (float)s;
    }
    __syncthreads();
    for (int e = tid; e < DD * DD; e += blockDim.x) {
        int a = e >> 5, b = e & 31;
        float s = 0.f;
        for (int m = 0; m < MMQ; m++) s += G[m * DD + a] * sAinvG[m][b];
        sP[a][b] = s;
        g_IPT[b * DD + a] = ((a == b) ? 1.0f : 0.0f) - s;
    }
    __syncthreads();
    if (tid == 0) {
        float tr = 0.f;
        for (int a = 0; a < DD; a++) tr += sP[a][a];
        g_trP = tr;
        g_t1v = 2.0f * T[0];
        g_count = 0u;
        g_gen = 0u;
    }
    // C = IP @ W3  (32 x 128)
    for (int e = tid; e < DD * HH; e += blockDim.x) {
        int a = e >> 7, j = e & 127;
        float s = 0.f;
        for (int b = 0; b < DD; b++)
            s += (((a == b) ? 1.0f : 0.0f) - sP[a][b]) * W3[b * HH + j];
        sC[a][j] = s;
    }
    __syncthreads();
    // MmatT[j][i] = W2[j,i] * B[i,j],  B = W1 @ C
    for (int e = tid; e < HH * HH; e += blockDim.x) {
        int j = e >> 7, i = e & 127;
        float s = 0.f;
        for (int a = 0; a < DD; a++) s += W1[i * DD + a] * sC[a][j];
        g_MmatT[j * HH + i] = s * W2[j * HH + i];
    }
}

// ---------------- init ----------------
__global__ void init_kernel(const float* __restrict__ z) {
    int total = NN * DD + NN;
    for (int i = blockIdx.x * blockDim.x + threadIdx.x; i < total; i += gridDim.x * blockDim.x) {
        if (i < NN * DD) g_yz[i] = z[i];
        else g_ylp[i - NN * DD] = 0.f;
    }
}

// ---------------- grid-wide barrier (co-resident grid: 128 CTAs, 1/SM) ----------------
__device__ __forceinline__ void grid_sync() {
    __syncthreads();
    if (threadIdx.x == 0) {
        unsigned old = g_gen;
        __threadfence();
        unsigned a = atomicAdd(&g_count, 1u);
        if (a == (unsigned)(NBLK - 1)) {
            g_count = 0u;
            __threadfence();
            g_gen = old + 1u;
        } else {
            while (g_gen == old) { __nanosleep(64); }
        }
        __threadfence();
    }
    __syncthreads();
}

// ---------------- persistent integrator ----------------
__global__ __launch_bounds__(TPB, 1) void persist_kernel(
    const float* __restrict__ W1, const float* __restrict__ b1,
    const float* __restrict__ W2, const float* __restrict__ b2,
    const float* __restrict__ W3, const float* __restrict__ b3,
    float* __restrict__ out) {
    extern __shared__ float sm[];
    float* sW1 = sm;                        // HH*P36
    float* sW2 = sW1 + HH * P36;            // HH*P132
    float* sMT = sW2 + HH * P132;           // HH*P132
    float* sW3 = sMT + HH * P132;           // DD*P132
    float* sIPT = sW3 + DD * P132;          // DD*P36
    float* sb1 = sIPT + DD * P36;           // HH
    float* sb2 = sb1 + HH;                  // HH
    float* sb3 = sb2 + HH;                  // DD
    float* sred = sb3 + DD;                 // 32
    float* xs = sred + 32;                  // 16*SPW*DD
    float* hs = xs + 16 * SPW * DD;         // 16*SPW*HH

    int tid = threadIdx.x;
    int w = tid >> 5, lane = tid & 31;
    int n0 = (blockIdx.x * (TPB / 32) + w) * SPW;
    float* xw = xs + w * (SPW * DD);
    float* hw = hs + w * (SPW * HH);

    // ---- stage weights ONCE
    for (int e = tid; e < HH * DD; e += TPB) sW1[(e >> 5) * P36 + (e & 31)] = W1[e];
    for (int e = tid; e < HH * HH; e += TPB) sW2[(e >> 7) * P132 + (e & 127)] = W2[e];
    for (int e = tid; e < HH * HH; e += TPB) sMT[(e >> 7) * P132 + (e & 127)] = g_MmatT[e];
    for (int e = tid; e < DD * HH; e += TPB) sW3[(e >> 7) * P132 + (e & 127)] = W3[e];
    for (int e = tid; e < DD * DD; e += TPB) sIPT[(e >> 5) * P36 + (e & 31)] = g_IPT[e];
    if (tid < HH) { sb1[tid] = b1[tid]; sb2[tid] = b2[tid]; }
    if (tid < DD) sb3[tid] = b3[tid];
    __syncthreads();

    float trP = g_trP;
    float t1 = g_t1v;
    // per-thread controller state (identical on every thread/CTA)
    float t = 0.f, dt = 0.25f;
    int done = (0.f >= t1 - 1e-9f) ? 1 : 0;
    float dtc = done ? 0.001f : fminf(dt, t1);
    int accept = 0;

    for (int step = 0; step < NSTEPS; step++) {
        for (int st = 0; st < 7; st++) {
            int mode = (st == 0) ? 1 : ((st == 6) ? 2 : 0);

            // ---- stage input x
            float xv[SPW];
            if (mode == 1) {
#pragma unroll
                for (int s = 0; s < SPW; s++) {
                    int nd = (n0 + s) * DD + lane;
                    float v = accept ? g_y1z[nd] : g_yz[nd];
                    if (accept) g_yz[nd] = v;
                    xv[s] = v;
                    xw[s * DD + lane] = v;
                }
                if (lane < SPW && accept) {
                    int n = n0 + lane;
                    g_ylp[n] = g_y1lp[n];
                }
            } else if (mode == 2) {
#pragma unroll
                for (int s = 0; s < SPW; s++) {
                    int nd = (n0 + s) * DD + lane;
                    float yv = g_yz[nd];
                    float acc = C1f * g_kz[0][nd] + C3f * g_kz[2][nd] + C4f * g_kz[3][nd] +
                                C5f * g_kz[4][nd] + C6f * g_kz[5][nd];
                    float y1 = yv + dtc * acc;
                    g_y1z[nd] = y1;
                    xv[s] = y1;
                    xw[s * DD + lane] = y1;
                }
            } else {
                float a0 = A_TAB[st][0], a1 = A_TAB[st][1], a2 = A_TAB[st][2],
                      a3 = A_TAB[st][3], a4 = A_TAB[st][4];
                int nk = NK_TAB[st];
#pragma unroll
                for (int s = 0; s < SPW; s++) {
                    int nd = (n0 + s) * DD + lane;
                    float v = g_yz[nd];
                    float acc = a0 * g_kz[0][nd];
                    if (nk > 1) acc += a1 * g_kz[1][nd];
                    if (nk > 2) acc += a2 * g_kz[2][nd];
                    if (nk > 3) acc += a3 * g_kz[3][nd];
                    if (nk > 4) acc += a4 * g_kz[4][nd];
                    v += dtc * acc;
                    xv[s] = v;
                    xw[s * DD + lane] = v;
                }
            }
            __syncwarp();

            // pass 1: h1pre = W1 @ x + b1 (lane owns j = c*32+lane)
            float h1[SPW][4];
#pragma unroll
            for (int s = 0; s < SPW; s++)
#pragma unroll
                for (int c = 0; c < 4; c++) h1[s][c] = sb1[c * 32 + lane];
#pragma unroll
            for (int d0 = 0; d0 < DD; d0 += 4) {
                float4 x4[SPW];
#pragma unroll
                for (int s = 0; s < SPW; s++) x4[s] = *(const float4*)&xw[s * DD + d0];
#pragma unroll
                for (int c = 0; c < 4; c++) {
                    float4 wv = *(const float4*)&sW1[(c * 32 + lane) * P36 + d0];
#pragma unroll
                    for (int s = 0; s < SPW; s++)
                        h1[s][c] += wv.x * x4[s].x + wv.y * x4[s].y + wv.z * x4[s].z + wv.w * x4[s].w;
                }
            }
#pragma unroll
            for (int s = 0; s < SPW; s++)
#pragma unroll
                for (int c = 0; c < 4; c++) hw[s * HH + c * 32 + lane] = fmaxf(h1[s][c], 0.f);
            __syncwarp();

            // pass 2: h2pre = W2 @ relu(h1) + b2, v[j] = sum_i MT[j][i]*mask(h1[i])
            float h2[SPW][4], vv[SPW][4];
#pragma unroll
            for (int s = 0; s < SPW; s++)
#pragma unroll
                for (int c = 0; c < 4; c++) {
                    h2[s][c] = sb2[c * 32 + lane];
                    vv[s][c] = 0.f;
                }
            for (int i0 = 0; i0 < HH; i0 += 4) {
                float4 h4[SPW], m4[SPW];
#pragma unroll
                for (int s = 0; s < SPW; s++) {
                    h4[s] = *(const float4*)&hw[s * HH + i0];
                    m4[s].x = h4[s].x > 0.f ? 1.f : 0.f;
                    m4[s].y = h4[s].y > 0.f ? 1.f : 0.f;
                    m4[s].z = h4[s].z > 0.f ? 1.f : 0.f;
                    m4[s].w = h4[s].w > 0.f ? 1.f : 0.f;
                }
#pragma unroll
                for (int c = 0; c < 4; c++) {
                    int j = c * 32 + lane;
                    float4 w2 = *(const float4*)&sW2[j * P132 + i0];
                    float4 mm = *(const float4*)&sMT[j * P132 + i0];
#pragma unroll
                    for (int s = 0; s < SPW; s++) {
                        h2[s][c] += w2.x * h4[s].x + w2.y * h4[s].y + w2.z * h4[s].z + w2.w * h4[s].w;
                        vv[s][c] += mm.x * m4[s].x + mm.y * m4[s].y + mm.z * m4[s].z + mm.w * m4[s].w;
                    }
                }
            }
            __syncwarp();
            float dlp[SPW];
#pragma unroll
            for (int s = 0; s < SPW; s++) {
                float acc = 0.f;
#pragma unroll
                for (int c = 0; c < 4; c++) {
                    float h2v = h2[s][c];
                    hw[s * HH + c * 32 + lane] = fmaxf(h2v, 0.f);
                    if (h2v > 0.f) acc += vv[s][c];
                }
                dlp[s] = acc;
            }
            __syncwarp();

            // pass 3: dF = W3 @ relu(h2) + b3 (lane owns d = lane)
            float dF[SPW];
#pragma unroll
            for (int s = 0; s < SPW; s++) dF[s] = sb3[lane];
            for (int h0 = 0; h0 < HH; h0 += 4) {
                float4 w3 = *(const float4*)&sW3[lane * P132 + h0];
#pragma unroll
                for (int s = 0; s < SPW; s++) {
                    float4 h24 = *(const float4*)&hw[s * HH + h0];
                    dF[s] += w3.x * h24.x + w3.y * h24.y + w3.z * h24.z + w3.w * h24.w;
                }
            }
            __syncwarp();
#pragma unroll
            for (int s = 0; s < SPW; s++) hw[s * HH + lane] = xv[s] - dF[s];
            __syncwarp();

            // pass 4: dz = (x - dF) @ IP - x
            float dz[SPW];
#pragma unroll
            for (int s = 0; s < SPW; s++) dz[s] = -xv[s];
#pragma unroll
            for (int k0 = 0; k0 < DD; k0 += 4) {
                float4 ip = *(const float4*)&sIPT[lane * P36 + k0];
#pragma unroll
                for (int s = 0; s < SPW; s++) {
                    float4 t4 = *(const float4*)&hw[s * HH + k0];
                    dz[s] += ip.x * t4.x + ip.y * t4.y + ip.z * t4.z + ip.w * t4.w;
                }
            }

            // ---- epilogue
            float dlpAll[SPW];
#pragma unroll
            for (int s = 0; s < SPW; s++) {
                float v = dlp[s];
#pragma unroll
                for (int off = 16; off > 0; off >>= 1) v += __shfl_xor_sync(0xffffffffu, v, off);
                dlpAll[s] = v + trP;
            }

            if (mode != 2) {
#pragma unroll
                for (int s = 0; s < SPW; s++) {
                    int n = n0 + s;
                    g_kz[st][n * DD + lane] = dz[s];
                    if (lane == 0) g_klp[st][n] = dlpAll[s];
                }
            } else {
                float acc = 0.f;
#pragma unroll
                for (int s = 0; s < SPW; s++) {
                    int nd = (n0 + s) * DD + lane;
                    float yv = g_yz[nd];
                    float ev = dtc * (E1f * g_kz[0][nd] + E3f * g_kz[2][nd] + E4f * g_kz[3][nd] +
                                      E5f * g_kz[4][nd] + E6f * g_kz[5][nd] + E7f * dz[s]);
                    float tol = 1e-5f + 1e-5f * fmaxf(fabsf(yv), fabsf(xv[s]));
                    float r = ev / tol;
                    acc += r * r;
                }
                if (lane < SPW) {
                    int s = lane;
                    int n = n0 + s;
                    float k0l = g_klp[0][n], k2l = g_klp[2][n], k3l = g_klp[3][n],
                          k4l = g_klp[4][n], k5l = g_klp[5][n];
                    float ylp = g_ylp[n];
                    float y1lp = ylp + dtc * (C1f * k0l + C3f * k2l + C4f * k3l + C5f * k4l + C6f * k5l);
                    g_y1lp[n] = y1lp;
                    float ev = dtc * (E1f * k0l + E3f * k2l + E4f * k3l + E5f * k4l + E6f * k5l +
                                      E7f * dlpAll[s]);
                    float tol = 1e-5f + 1e-5f * fmaxf(fabsf(ylp), fabsf(y1lp));
                    float r = ev / tol;
                    acc += r * r;
                }
#pragma unroll
                for (int off = 16; off > 0; off >>= 1) acc += __shfl_xor_sync(0xffffffffu, acc, off);
                if (lane == 0) sred[w] = acc;
                __syncthreads();
                if (w == 0) {
                    float v = sred[lane] + sred[lane + 16];
                    v += __shfl_xor_sync(0xffffffffu, v, 8);
                    v += __shfl_xor_sync(0xffffffffu, v, 4);
                    v += __shfl_xor_sync(0xffffffffu, v, 2);
                    v += __shfl_xor_sync(0xffffffffu, v, 1);
                    if (lane == 0) g_partial[step & 1][blockIdx.x] = v;
                }
            }
        }  // stages

        grid_sync();

        // ---- controller (computed identically by every warp of every CTA)
        const float* pp = &g_partial[step & 1][0];
        float v = __ldcg(&pp[lane]) + __ldcg(&pp[lane + 32]) +
                  __ldcg(&pp[lane + 64]) + __ldcg(&pp[lane + 96]);
#pragma unroll
        for (int off = 16; off > 0; off >>= 1) v += __shfl_xor_sync(0xffffffffu, v, off);
        float errn = sqrtf(v / (float)(NN * (DD + 1)));
        int done_cur = done;
        accept = (!done_cur) && (errn <= 1.0f);
        if (accept) t += dtc;
        float factor = (errn > 0.f) ? 0.9f * powf(errn, -0.2f) : 10.0f;
        factor = fminf(fmaxf(factor, 0.2f), 10.0f);
        if (!done_cur) dt = fminf(fmaxf(dtc * factor, 1e-6f), t1);
        done = (t >= t1 - 1e-9f) ? 1 : 0;
        dtc = done ? 0.001f : fminf(dt, t1 - t);
    }  // steps

    // ---- final output with pending accept
#pragma unroll
    for (int s = 0; s < SPW; s++) {
        int nd = (n0 + s) * DD + lane;
        out[nd] = accept ? g_y1z[nd] : g_yz[nd];
    }
}

// ---------------- launch ----------------
extern "C" void kernel_launch(void* const* d_in, const int* in_sizes, int n_in,
                              void* d_out, int out_size) {
    const float* z  = (const float*)d_in[0];
    const float* G  = (const float*)d_in[1];
    const float* W1 = (const float*)d_in[2];
    const float* b1 = (const float*)d_in[3];
    const float* W2 = (const float*)d_in[4];
    const float* b2 = (const float*)d_in[5];
    const float* W3 = (const float*)d_in[6];
    const float* b3 = (const float*)d_in[7];
    const float* T  = (const float*)d_in[8];

    const int smem_floats = HH * P36 + 2 * HH * P132 + DD * P132 + DD * P36 +
                            2 * HH + DD + 32 + 16 * SPW * DD + 16 * SPW * HH;
    const int smem_bytes = smem_floats * 4;
    cudaFuncSetAttribute(persist_kernel, cudaFuncAttributeMaxDynamicSharedMemorySize, smem_bytes);

    prep_kernel<<<1, 256>>>(G, W1, W2, W3, T);
    init_kernel<<<256, 256>>>(z);
    persist_kernel<<<NBLK, TPB, smem_bytes>>>(W1, b1, W2, b2, W3, b3, (float*)d_out);
}

// round 11
// speedup vs baseline: 1.8692x; 1.2132x over previous
#include <cuda_runtime.h>
#include <math.h>
#include <stdint.h>

#define NN 8192
#define DD 32
#define HH 128
#define MMQ 8
#define TPB 512
#define NBLK 128
#define SPW 4
#define P36 36
#define P132 132
#define NSTEPS 10

// ---------------- device state ----------------
__device__ float g_yz[NN * DD];
__device__ float g_ylp[NN];
__device__ float g_y1z[NN * DD];
__device__ float g_y1lp[NN];
__device__ float g_kz[6][NN * DD];
__device__ float g_klp[6][NN];
__device__ float g_partial[2][NBLK];
__device__ unsigned g_count = 0u;          // self-restoring across replays
__device__ volatile unsigned g_gen = 0u;   // monotonic; barrier compares relatively

// RK45 combine/error coefficients
#define C1f ((float)(35.0 / 384.0))
#define C3f ((float)(500.0 / 1113.0))
#define C4f ((float)(125.0 / 192.0))
#define C5f ((float)(-2187.0 / 6784.0))
#define C6f ((float)(11.0 / 84.0))
#define E1f ((float)(35.0 / 384.0 - 5179.0 / 57600.0))
#define E3f ((float)(500.0 / 1113.0 - 7571.0 / 16695.0))
#define E4f ((float)(125.0 / 192.0 - 393.0 / 640.0))
#define E5f ((float)(-2187.0 / 6784.0 + 92097.0 / 339200.0))
#define E6f ((float)(11.0 / 84.0 - 187.0 / 2100.0))
#define E7f ((float)(-1.0 / 40.0))

__constant__ float A_TAB[7][5] = {
    {0.f, 0.f, 0.f, 0.f, 0.f},
    {0.2f, 0.f, 0.f, 0.f, 0.f},
    {(float)(3.0 / 40.0), (float)(9.0 / 40.0), 0.f, 0.f, 0.f},
    {(float)(44.0 / 45.0), (float)(-56.0 / 15.0), (float)(32.0 / 9.0), 0.f, 0.f},
    {(float)(19372.0 / 6561.0), (float)(-25360.0 / 2187.0), (float)(64448.0 / 6561.0),
     (float)(-212.0 / 729.0), 0.f},
    {(float)(9017.0 / 3168.0), (float)(-355.0 / 33.0), (float)(46732.0 / 5247.0),
     (float)(49.0 / 176.0), (float)(-5103.0 / 18656.0)},
    {0.f, 0.f, 0.f, 0.f, 0.f}};
__constant__ int NK_TAB[7] = {0, 1, 2, 3, 4, 5, 0};

// ---------------- grid-wide barrier (co-resident grid: 128 CTAs, 1/SM) ----------------
__device__ __forceinline__ void grid_sync() {
    __syncthreads();
    if (threadIdx.x == 0) {
        unsigned old = g_gen;
        __threadfence();
        unsigned a = atomicAdd(&g_count, 1u);
        if (a == (unsigned)(NBLK - 1)) {
            g_count = 0u;
            __threadfence();
            g_gen = old + 1u;
        } else {
            while (g_gen == old) { __nanosleep(64); }
        }
        __threadfence();
    }
    __syncthreads();
}

// ---------------- single persistent kernel: prep + init + integrate ----------------
__global__ __launch_bounds__(TPB, 1) void persist_kernel(
    const float* __restrict__ z, const float* __restrict__ G,
    const float* __restrict__ W1, const float* __restrict__ b1,
    const float* __restrict__ W2, const float* __restrict__ b2,
    const float* __restrict__ W3, const float* __restrict__ b3,
    const float* __restrict__ T, float* __restrict__ out) {
    extern __shared__ float sm[];
    float* sW1 = sm;                        // HH*P36
    float* sW2 = sW1 + HH * P36;            // HH*P132
    float* sMT = sW2 + HH * P132;           // HH*P132
    float* sW3 = sMT + HH * P132;           // DD*P132
    float* sIPT = sW3 + DD * P132;          // DD*P36
    float* sb1 = sIPT + DD * P36;           // HH
    float* sb2 = sb1 + HH;                  // HH
    float* sb3 = sb2 + HH;                  // DD
    float* sred = sb3 + DD;                 // 32
    float* xs = sred + 32;                  // 16*SPW*DD = 2048
    float* hs = xs + 16 * SPW * DD;         // 16*SPW*HH = 8192

    int tid = threadIdx.x;
    int w = tid >> 5, lane = tid & 31;
    int n0 = (blockIdx.x * (TPB / 32) + w) * SPW;
    float* xw = xs + w * (SPW * DD);
    float* hw = hs + w * (SPW * HH);

    // ================= PHASE A: weight staging =================
    for (int e = tid; e < HH * DD; e += TPB) sW1[(e >> 5) * P36 + (e & 31)] = W1[e];
    for (int e = tid; e < HH * HH; e += TPB) sW2[(e >> 7) * P132 + (e & 127)] = W2[e];
    for (int e = tid; e < DD * HH; e += TPB) sW3[(e >> 7) * P132 + (e & 127)] = W3[e];
    if (tid < HH) { sb1[tid] = b1[tid]; sb2[tid] = b2[tid]; }
    if (tid < DD) sb3[tid] = b3[tid];

    // ================= PHASE B: prep (redundant per CTA, in shared) =================
    // scratch layout (pre-mainloop only):
    //   xs:  sG (256) + sP (1024)
    //   hs:  sC (4096) + Mx (128 doubles = 256 floats) + Ad (64 doubles = 128 floats)
    //        + sAinvG (256 floats)
    float* sG = xs;            // 8x32
    float* sP = xs + 256;      // 32x32
    float* sC = hs;            // 32x128
    double* Mx = (double*)(hs + 4096);       // 8x16 augmented
    double* Ad = (double*)(hs + 4096 + 256); // 8x8
    float* sAinvG = hs + 4096 + 256 + 128;   // 8x32

    if (tid < MMQ * DD) sG[tid] = G[tid];
    __syncthreads();

    // A = G G^T (double)
    if (tid < MMQ * MMQ) {
        int i = tid >> 3, j = tid & 7;
        double s = 0.0;
        for (int d = 0; d < DD; d++) s += (double)sG[i * DD + d] * (double)sG[j * DD + d];
        Ad[i * MMQ + j] = s;
    }
    __syncthreads();

    // parallel Gauss-Jordan inverse of A in shared doubles (threads 0..127 active)
    {
        int r = tid >> 4, j = tid & 15;
        if (tid < 128) Mx[r * 16 + j] = (j < MMQ) ? Ad[r * MMQ + j] : (((j - MMQ) == r) ? 1.0 : 0.0);
        __syncthreads();
        for (int col = 0; col < MMQ; col++) {
            // pivot search (redundant, deterministic)
            int piv = col;
            double best = fabs(Mx[col * 16 + col]);
            for (int r2 = col + 1; r2 < MMQ; r2++) {
                double v = fabs(Mx[r2 * 16 + col]);
                if (v > best) { best = v; piv = r2; }
            }
            if (piv != col && tid < 16) {
                double tmp = Mx[col * 16 + tid];
                Mx[col * 16 + tid] = Mx[piv * 16 + tid];
                Mx[piv * 16 + tid] = tmp;
            }
            __syncthreads();
            double invp = 1.0 / Mx[col * 16 + col];
            __syncthreads();
            if (tid < 16) Mx[col * 16 + tid] *= invp;
            __syncthreads();
            double f = 0.0, pcj = 0.0;
            if (tid < 128 && r != col) f = Mx[r * 16 + col];
            if (tid < 128) pcj = Mx[col * 16 + j];
            __syncthreads();
            if (tid < 128 && r != col) Mx[r * 16 + j] -= f * pcj;
            __syncthreads();
        }
    }
    // AinvG (double accum, float store) — Ainv[i][k] = Mx[i*16+8+k]
    if (tid < MMQ * DD) {
        int m = tid >> 5, d = tid & 31;
        double s = 0.0;
        for (int k = 0; k < MMQ; k++) s += Mx[m * 16 + MMQ + k] * (double)sG[k * DD + d];
        sAinvG[m * DD + d] = (float)s;
    }
    __syncthreads();
    // P and IPT (float)
    for (int e = tid; e < DD * DD; e += TPB) {
        int a = e >> 5, b = e & 31;
        float s = 0.f;
        for (int m = 0; m < MMQ; m++) s += sG[m * DD + a] * sAinvG[m * DD + b];
        sP[a * DD + b] = s;
        sIPT[b * P36 + a] = ((a == b) ? 1.0f : 0.0f) - s;
    }
    __syncthreads();
    // trP (redundant)
    float trP = 0.f;
    for (int a = 0; a < DD; a++) trP += sP[a * DD + a];
    // C = IP @ W3 (32 x 128)
    for (int e = tid; e < DD * HH; e += TPB) {
        int a = e >> 7, j = e & 127;
        float s = 0.f;
        for (int b = 0; b < DD; b++)
            s += (((a == b) ? 1.0f : 0.0f) - sP[a * DD + b]) * sW3[b * P132 + j];
        sC[a * HH + j] = s;
    }
    __syncthreads();
    // MmatT[j][i] = (W1[i]·C[:,j]) * W2[j,i]
    for (int e = tid; e < HH * HH; e += TPB) {
        int j = e >> 7, i = e & 127;
        float s = 0.f;
        for (int a = 0; a < DD; a++) s += sW1[i * P36 + a] * sC[a * HH + j];
        sMT[j * P132 + i] = s * sW2[j * P132 + i];
    }

    // ================= PHASE C: init own samples =================
#pragma unroll
    for (int s = 0; s < SPW; s++) {
        int nd = (n0 + s) * DD + lane;
        g_yz[nd] = z[nd];
    }
    if (lane < SPW) g_ylp[n0 + lane] = 0.f;

    float t1 = 2.0f * T[0];
    __syncthreads();  // sMT/sC scratch done before main loop reuses hs/xs

    // ================= PHASE D: integrate =================
    float t = 0.f, dt = 0.25f;
    int done = (0.f >= t1 - 1e-9f) ? 1 : 0;
    float dtc = done ? 0.001f : fminf(dt, t1);
    int accept = 0;

    for (int step = 0; step < NSTEPS; step++) {
        for (int st = 0; st < 7; st++) {
            int mode = (st == 0) ? 1 : ((st == 6) ? 2 : 0);

            // ---- stage input x
            float xv[SPW];
            if (mode == 1) {
#pragma unroll
                for (int s = 0; s < SPW; s++) {
                    int nd = (n0 + s) * DD + lane;
                    float v = accept ? g_y1z[nd] : g_yz[nd];
                    if (accept) g_yz[nd] = v;
                    xv[s] = v;
                    xw[s * DD + lane] = v;
                }
                if (lane < SPW && accept) {
                    int n = n0 + lane;
                    g_ylp[n] = g_y1lp[n];
                }
            } else if (mode == 2) {
#pragma unroll
                for (int s = 0; s < SPW; s++) {
                    int nd = (n0 + s) * DD + lane;
                    float yv = g_yz[nd];
                    float acc = C1f * g_kz[0][nd] + C3f * g_kz[2][nd] + C4f * g_kz[3][nd] +
                                C5f * g_kz[4][nd] + C6f * g_kz[5][nd];
                    float y1 = yv + dtc * acc;
                    g_y1z[nd] = y1;
                    xv[s] = y1;
                    xw[s * DD + lane] = y1;
                }
            } else {
                float a0 = A_TAB[st][0], a1 = A_TAB[st][1], a2 = A_TAB[st][2],
                      a3 = A_TAB[st][3], a4 = A_TAB[st][4];
                int nk = NK_TAB[st];
#pragma unroll
                for (int s = 0; s < SPW; s++) {
                    int nd = (n0 + s) * DD + lane;
                    float v = g_yz[nd];
                    float acc = a0 * g_kz[0][nd];
                    if (nk > 1) acc += a1 * g_kz[1][nd];
                    if (nk > 2) acc += a2 * g_kz[2][nd];
                    if (nk > 3) acc += a3 * g_kz[3][nd];
                    if (nk > 4) acc += a4 * g_kz[4][nd];
                    v += dtc * acc;
                    xv[s] = v;
                    xw[s * DD + lane] = v;
                }
            }
            __syncwarp();

            // pass 1: h1pre = W1 @ x + b1 (lane owns j = c*32+lane)
            float h1[SPW][4];
#pragma unroll
            for (int s = 0; s < SPW; s++)
#pragma unroll
                for (int c = 0; c < 4; c++) h1[s][c] = sb1[c * 32 + lane];
#pragma unroll
            for (int d0 = 0; d0 < DD; d0 += 4) {
                float4 x4[SPW];
#pragma unroll
                for (int s = 0; s < SPW; s++) x4[s] = *(const float4*)&xw[s * DD + d0];
#pragma unroll
                for (int c = 0; c < 4; c++) {
                    float4 wv = *(const float4*)&sW1[(c * 32 + lane) * P36 + d0];
#pragma unroll
                    for (int s = 0; s < SPW; s++)
                        h1[s][c] += wv.x * x4[s].x + wv.y * x4[s].y + wv.z * x4[s].z + wv.w * x4[s].w;
                }
            }
#pragma unroll
            for (int s = 0; s < SPW; s++)
#pragma unroll
                for (int c = 0; c < 4; c++) hw[s * HH + c * 32 + lane] = fmaxf(h1[s][c], 0.f);
            __syncwarp();

            // pass 2: h2pre = W2 @ relu(h1) + b2, v[j] = sum_i MT[j][i]*mask(h1[i])
            float h2[SPW][4], vv[SPW][4];
#pragma unroll
            for (int s = 0; s < SPW; s++)
#pragma unroll
                for (int c = 0; c < 4; c++) {
                    h2[s][c] = sb2[c * 32 + lane];
                    vv[s][c] = 0.f;
                }
            for (int i0 = 0; i0 < HH; i0 += 4) {
                float4 h4[SPW], m4[SPW];
#pragma unroll
                for (int s = 0; s < SPW; s++) {
                    h4[s] = *(const float4*)&hw[s * HH + i0];
                    m4[s].x = h4[s].x > 0.f ? 1.f : 0.f;
                    m4[s].y = h4[s].y > 0.f ? 1.f : 0.f;
                    m4[s].z = h4[s].z > 0.f ? 1.f : 0.f;
                    m4[s].w = h4[s].w > 0.f ? 1.f : 0.f;
                }
#pragma unroll
                for (int c = 0; c < 4; c++) {
                    int j = c * 32 + lane;
                    float4 w2 = *(const float4*)&sW2[j * P132 + i0];
                    float4 mm = *(const float4*)&sMT[j * P132 + i0];
#pragma unroll
                    for (int s = 0; s < SPW; s++) {
                        h2[s][c] += w2.x * h4[s].x + w2.y * h4[s].y + w2.z * h4[s].z + w2.w * h4[s].w;
                        vv[s][c] += mm.x * m4[s].x + mm.y * m4[s].y + mm.z * m4[s].z + mm.w * m4[s].w;
                    }
                }
            }
            __syncwarp();
            float dlp[SPW];
#pragma unroll
            for (int s = 0; s < SPW; s++) {
                float acc = 0.f;
#pragma unroll
                for (int c = 0; c < 4; c++) {
                    float h2v = h2[s][c];
                    hw[s * HH + c * 32 + lane] = fmaxf(h2v, 0.f);
                    if (h2v > 0.f) acc += vv[s][c];
                }
                dlp[s] = acc;
            }
            __syncwarp();

            // pass 3: dF = W3 @ relu(h2) + b3 (lane owns d = lane)
            float dF[SPW];
#pragma unroll
            for (int s = 0; s < SPW; s++) dF[s] = sb3[lane];
            for (int h0 = 0; h0 < HH; h0 += 4) {
                float4 w3 = *(const float4*)&sW3[lane * P132 + h0];
#pragma unroll
                for (int s = 0; s < SPW; s++) {
                    float4 h24 = *(const float4*)&hw[s * HH + h0];
                    dF[s] += w3.x * h24.x + w3.y * h24.y + w3.z * h24.z + w3.w * h24.w;
                }
            }
            __syncwarp();
#pragma unroll
            for (int s = 0; s < SPW; s++) hw[s * HH + lane] = xv[s] - dF[s];
            __syncwarp();

            // pass 4: dz = (x - dF) @ IP - x
            float dz[SPW];
#pragma unroll
            for (int s = 0; s < SPW; s++) dz[s] = -xv[s];
#pragma unroll
            for (int k0 = 0; k0 < DD; k0 += 4) {
                float4 ip = *(const float4*)&sIPT[lane * P36 + k0];
#pragma unroll
                for (int s = 0; s < SPW; s++) {
                    float4 t4 = *(const float4*)&hw[s * HH + k0];
                    dz[s] += ip.x * t4.x + ip.y * t4.y + ip.z * t4.z + ip.w * t4.w;
                }
            }

            // ---- epilogue
            float dlpAll[SPW];
#pragma unroll
            for (int s = 0; s < SPW; s++) {
                float v = dlp[s];
#pragma unroll
                for (int off = 16; off > 0; off >>= 1) v += __shfl_xor_sync(0xffffffffu, v, off);
                dlpAll[s] = v + trP;
            }

            if (mode != 2) {
#pragma unroll
                for (int s = 0; s < SPW; s++) {
                    int n = n0 + s;
                    g_kz[st][n * DD + lane] = dz[s];
                    if (lane == 0) g_klp[st][n] = dlpAll[s];
                }
            } else {
                float acc = 0.f;
#pragma unroll
                for (int s = 0; s < SPW; s++) {
                    int nd = (n0 + s) * DD + lane;
                    float yv = g_yz[nd];
                    float ev = dtc * (E1f * g_kz[0][nd] + E3f * g_kz[2][nd] + E4f * g_kz[3][nd] +
                                      E5f * g_kz[4][nd] + E6f * g_kz[5][nd] + E7f * dz[s]);
                    float tol = 1e-5f + 1e-5f * fmaxf(fabsf(yv), fabsf(xv[s]));
                    float r = ev / tol;
                    acc += r * r;
                }
                if (lane < SPW) {
                    int s = lane;
                    int n = n0 + s;
                    float k0l = g_klp[0][n], k2l = g_klp[2][n], k3l = g_klp[3][n],
                          k4l = g_klp[4][n], k5l = g_klp[5][n];
                    float ylp = g_ylp[n];
                    float y1lp = ylp + dtc * (C1f * k0l + C3f * k2l + C4f * k3l + C5f * k4l + C6f * k5l);
                    g_y1lp[n] = y1lp;
                    float ev = dtc * (E1f * k0l + E3f * k2l + E4f * k3l + E5f * k4l + E6f * k5l +
                                      E7f * dlpAll[s]);
                    float tol = 1e-5f + 1e-5f * fmaxf(fabsf(ylp), fabsf(y1lp));
                    float r = ev / tol;
                    acc += r * r;
                }
#pragma unroll
                for (int off = 16; off > 0; off >>= 1) acc += __shfl_xor_sync(0xffffffffu, acc, off);
                if (lane == 0) sred[w] = acc;
                __syncthreads();
                if (w == 0) {
                    float v = sred[lane] + sred[lane + 16];
                    v += __shfl_xor_sync(0xffffffffu, v, 8);
                    v += __shfl_xor_sync(0xffffffffu, v, 4);
                    v += __shfl_xor_sync(0xffffffffu, v, 2);
                    v += __shfl_xor_sync(0xffffffffu, v, 1);
                    if (lane == 0) g_partial[step & 1][blockIdx.x] = v;
                }
            }
        }  // stages

        grid_sync();

        // ---- controller (computed identically by every warp of every CTA)
        const float* pp = &g_partial[step & 1][0];
        float v = __ldcg(&pp[lane]) + __ldcg(&pp[lane + 32]) +
                  __ldcg(&pp[lane + 64]) + __ldcg(&pp[lane + 96]);
#pragma unroll
        for (int off = 16; off > 0; off >>= 1) v += __shfl_xor_sync(0xffffffffu, v, off);
        float errn = sqrtf(v / (float)(NN * (DD + 1)));
        int done_cur = done;
        accept = (!done_cur) && (errn <= 1.0f);
        if (accept) t += dtc;
        float factor = (errn > 0.f) ? 0.9f * powf(errn, -0.2f) : 10.0f;
        factor = fminf(fmaxf(factor, 0.2f), 10.0f);
        if (!done_cur) dt = fminf(fmaxf(dtc * factor, 1e-6f), t1);
        done = (t >= t1 - 1e-9f) ? 1 : 0;
        dtc = done ? 0.001f : fminf(dt, t1 - t);
    }  // steps

    // ---- final output with pending accept
#pragma unroll
    for (int s = 0; s < SPW; s++) {
        int nd = (n0 + s) * DD + lane;
        out[nd] = accept ? g_y1z[nd] : g_yz[nd];
    }
}

// ---------------- launch ----------------
extern "C" void kernel_launch(void* const* d_in, const int* in_sizes, int n_in,
                              void* d_out, int out_size) {
    const float* z  = (const float*)d_in[0];
    const float* G  = (const float*)d_in[1];
    const float* W1 = (const float*)d_in[2];
    const float* b1 = (const float*)d_in[3];
    const float* W2 = (const float*)d_in[4];
    const float* b2 = (const float*)d_in[5];
    const float* W3 = (const float*)d_in[6];
    const float* b3 = (const float*)d_in[7];
    const float* T  = (const float*)d_in[8];

    const int smem_floats = HH * P36 + 2 * HH * P132 + DD * P132 + DD * P36 +
                            2 * HH + DD + 32 + 16 * SPW * DD + 16 * SPW * HH;
    const int smem_bytes = smem_floats * 4;
    cudaFuncSetAttribute(persist_kernel, cudaFuncAttributeMaxDynamicSharedMemorySize, smem_bytes);

    persist_kernel<<<NBLK, TPB, smem_bytes>>>(z, G, W1, b1, W2, b2, W3, b3, T, (float*)d_out);
}

// round 12
// speedup vs baseline: 2.1158x; 1.1319x over previous
#include <cuda_runtime.h>
#include <math.h>
#include <stdint.h>

#define NN 8192
#define DD 32
#define HH 128
#define MMQ 8
#define TPB 512
#define NBLK 128
#define SPW 4
#define P36 36
#define P132 132
#define PW 260   // interleaved (W2, MT) row pitch; 260 % 32 == 4 -> conflict-free
#define NSTEPS 10

// ---------------- device state ----------------
__device__ float g_yz[NN * DD];
__device__ float g_ylp[NN];
__device__ float g_y1z[NN * DD];
__device__ float g_y1lp[NN];
__device__ float g_kz[6][NN * DD];
__device__ float g_klp[6][NN];
__device__ float g_partial[2][NBLK];
__device__ unsigned g_count = 0u;          // self-restoring across replays
__device__ volatile unsigned g_gen = 0u;   // monotonic; barrier compares relatively

// RK45 combine/error coefficients
#define C1f ((float)(35.0 / 384.0))
#define C3f ((float)(500.0 / 1113.0))
#define C4f ((float)(125.0 / 192.0))
#define C5f ((float)(-2187.0 / 6784.0))
#define C6f ((float)(11.0 / 84.0))
#define E1f ((float)(35.0 / 384.0 - 5179.0 / 57600.0))
#define E3f ((float)(500.0 / 1113.0 - 7571.0 / 16695.0))
#define E4f ((float)(125.0 / 192.0 - 393.0 / 640.0))
#define E5f ((float)(-2187.0 / 6784.0 + 92097.0 / 339200.0))
#define E6f ((float)(11.0 / 84.0 - 187.0 / 2100.0))
#define E7f ((float)(-1.0 / 40.0))

__constant__ float A_TAB[7][5] = {
    {0.f, 0.f, 0.f, 0.f, 0.f},
    {0.2f, 0.f, 0.f, 0.f, 0.f},
    {(float)(3.0 / 40.0), (float)(9.0 / 40.0), 0.f, 0.f, 0.f},
    {(float)(44.0 / 45.0), (float)(-56.0 / 15.0), (float)(32.0 / 9.0), 0.f, 0.f},
    {(float)(19372.0 / 6561.0), (float)(-25360.0 / 2187.0), (float)(64448.0 / 6561.0),
     (float)(-212.0 / 729.0), 0.f},
    {(float)(9017.0 / 3168.0), (float)(-355.0 / 33.0), (float)(46732.0 / 5247.0),
     (float)(49.0 / 176.0), (float)(-5103.0 / 18656.0)},
    {0.f, 0.f, 0.f, 0.f, 0.f}};
__constant__ int NK_TAB[7] = {0, 1, 2, 3, 4, 5, 0};

// ---------------- packed f32x2 helpers ----------------
__device__ __forceinline__ void ffma2(unsigned long long& d, unsigned long long a,
                                      unsigned long long b) {
    asm("fma.rn.f32x2 %0, %1, %2, %0;" : "+l"(d) : "l"(a), "l"(b));
}
__device__ __forceinline__ unsigned long long pk2(float lo, float hi) {
    unsigned long long v;
    asm("mov.b64 %0, {%1, %2};" : "=l"(v) : "r"(__float_as_uint(lo)), "r"(__float_as_uint(hi)));
    return v;
}
__device__ __forceinline__ void upk2(unsigned long long v, float& lo, float& hi) {
    unsigned a, b;
    asm("mov.b64 {%0, %1}, %2;" : "=r"(a), "=r"(b) : "l"(v));
    lo = __uint_as_float(a);
    hi = __uint_as_float(b);
}

// ---------------- grid-wide barrier (co-resident grid: 128 CTAs, 1/SM) ----------------
__device__ __forceinline__ void grid_sync() {
    __syncthreads();
    if (threadIdx.x == 0) {
        unsigned old = g_gen;
        __threadfence();
        unsigned a = atomicAdd(&g_count, 1u);
        if (a == (unsigned)(NBLK - 1)) {
            g_count = 0u;
            __threadfence();
            g_gen = old + 1u;
        } else {
            while (g_gen == old) { __nanosleep(64); }
        }
        __threadfence();
    }
    __syncthreads();
}

// ---------------- single persistent kernel: prep + init + integrate ----------------
__global__ __launch_bounds__(TPB, 1) void persist_kernel(
    const float* __restrict__ z, const float* __restrict__ G,
    const float* __restrict__ W1, const float* __restrict__ b1,
    const float* __restrict__ W2, const float* __restrict__ b2,
    const float* __restrict__ W3, const float* __restrict__ b3,
    const float* __restrict__ T, float* __restrict__ out) {
    extern __shared__ float sm[];
    float* sW1 = sm;                        // HH*P36           = 4608
    float* sWM = sW1 + HH * P36;            // HH*PW            = 33280 (W2,MT interleaved)
    float* sW3 = sWM + HH * PW;             // DD*P132          = 4224
    float* sIPT = sW3 + DD * P132;          // DD*P36           = 1152
    float* sb1 = sIPT + DD * P36;           // HH
    float* sb2 = sb1 + HH;                  // HH
    float* sb3 = sb2 + HH;                  // DD
    float* sred = sb3 + DD;                 // 32
    float* xs = sred + 32;                  // 16*SPW*DD = 2048
    float* hs = xs + 16 * SPW * DD;         // 16*SPW*HH = 8192

    int tid = threadIdx.x;
    int w = tid >> 5, lane = tid & 31;
    int n0 = (blockIdx.x * (TPB / 32) + w) * SPW;
    float* xw = xs + w * (SPW * DD);
    float* hw = hs + w * (SPW * HH);

    // ================= PHASE A: weight staging (W1, W3, biases) =================
    for (int e = tid; e < HH * DD; e += TPB) sW1[(e >> 5) * P36 + (e & 31)] = W1[e];
    for (int e = tid; e < DD * HH; e += TPB) sW3[(e >> 7) * P132 + (e & 127)] = W3[e];
    if (tid < HH) { sb1[tid] = b1[tid]; sb2[tid] = b2[tid]; }
    if (tid < DD) sb3[tid] = b3[tid];

    // ================= PHASE B: prep (redundant per CTA, in shared) =================
    float* sG = xs;            // 8x32
    float* sP = xs + 256;      // 32x32
    float* sC = hs;            // 32x128
    double* Mx = (double*)(hs + 4096);       // 8x16 augmented
    double* Ad = (double*)(hs + 4096 + 256); // 8x8
    float* sAinvG = hs + 4096 + 256 + 128;   // 8x32

    if (tid < MMQ * DD) sG[tid] = G[tid];
    __syncthreads();

    if (tid < MMQ * MMQ) {
        int i = tid >> 3, j = tid & 7;
        double s = 0.0;
        for (int d = 0; d < DD; d++) s += (double)sG[i * DD + d] * (double)sG[j * DD + d];
        Ad[i * MMQ + j] = s;
    }
    __syncthreads();

    {
        int r = tid >> 4, j = tid & 15;
        if (tid < 128) Mx[r * 16 + j] = (j < MMQ) ? Ad[r * MMQ + j] : (((j - MMQ) == r) ? 1.0 : 0.0);
        __syncthreads();
        for (int col = 0; col < MMQ; col++) {
            int piv = col;
            double best = fabs(Mx[col * 16 + col]);
            for (int r2 = col + 1; r2 < MMQ; r2++) {
                double v = fabs(Mx[r2 * 16 + col]);
                if (v > best) { best = v; piv = r2; }
            }
            if (piv != col && tid < 16) {
                double tmp = Mx[col * 16 + tid];
                Mx[col * 16 + tid] = Mx[piv * 16 + tid];
                Mx[piv * 16 + tid] = tmp;
            }
            __syncthreads();
            double invp = 1.0 / Mx[col * 16 + col];
            __syncthreads();
            if (tid < 16) Mx[col * 16 + tid] *= invp;
            __syncthreads();
            double f = 0.0, pcj = 0.0;
            if (tid < 128 && r != col) f = Mx[r * 16 + col];
            if (tid < 128) pcj = Mx[col * 16 + j];
            __syncthreads();
            if (tid < 128 && r != col) Mx[r * 16 + j] -= f * pcj;
            __syncthreads();
        }
    }
    if (tid < MMQ * DD) {
        int m = tid >> 5, d = tid & 31;
        double s = 0.0;
        for (int k = 0; k < MMQ; k++) s += Mx[m * 16 + MMQ + k] * (double)sG[k * DD + d];
        sAinvG[m * DD + d] = (float)s;
    }
    __syncthreads();
    for (int e = tid; e < DD * DD; e += TPB) {
        int a = e >> 5, b = e & 31;
        float s = 0.f;
        for (int m = 0; m < MMQ; m++) s += sG[m * DD + a] * sAinvG[m * DD + b];
        sP[a * DD + b] = s;
        sIPT[b * P36 + a] = ((a == b) ? 1.0f : 0.0f) - s;
    }
    __syncthreads();
    float trP = 0.f;
    for (int a = 0; a < DD; a++) trP += sP[a * DD + a];
    for (int e = tid; e < DD * HH; e += TPB) {
        int a = e >> 7, j = e & 127;
        float s = 0.f;
        for (int b = 0; b < DD; b++)
            s += (((a == b) ? 1.0f : 0.0f) - sP[a * DD + b]) * sW3[b * P132 + j];
        sC[a * HH + j] = s;
    }
    __syncthreads();
    // interleaved weights: sWM[j][2i] = W2[j,i], sWM[j][2i+1] = MT[j,i] = B[i,j]*W2[j,i]
    for (int e = tid; e < HH * HH; e += TPB) {
        int j = e >> 7, i = e & 127;
        float s = 0.f;
        for (int a = 0; a < DD; a++) s += sW1[i * P36 + a] * sC[a * HH + j];
        float w2v = W2[j * HH + i];
        sWM[j * PW + 2 * i] = w2v;
        sWM[j * PW + 2 * i + 1] = s * w2v;
    }

    // ================= PHASE C: init own samples =================
#pragma unroll
    for (int s = 0; s < SPW; s++) {
        int nd = (n0 + s) * DD + lane;
        g_yz[nd] = z[nd];
    }
    if (lane < SPW) g_ylp[n0 + lane] = 0.f;

    float t1 = 2.0f * T[0];
    __syncthreads();  // prep scratch done before main loop reuses hs/xs

    // ================= PHASE D: integrate =================
    float t = 0.f, dt = 0.25f;
    int done = (0.f >= t1 - 1e-9f) ? 1 : 0;
    float dtc = done ? 0.001f : fminf(dt, t1);
    int accept = 0;

    for (int step = 0; step < NSTEPS; step++) {
        for (int st = 0; st < 7; st++) {
            int mode = (st == 0) ? 1 : ((st == 6) ? 2 : 0);

            // ---- stage input x
            float xv[SPW];
            if (mode == 1) {
#pragma unroll
                for (int s = 0; s < SPW; s++) {
                    int nd = (n0 + s) * DD + lane;
                    float v = accept ? g_y1z[nd] : g_yz[nd];
                    if (accept) g_yz[nd] = v;
                    xv[s] = v;
                    xw[s * DD + lane] = v;
                }
                if (lane < SPW && accept) {
                    int n = n0 + lane;
                    g_ylp[n] = g_y1lp[n];
                }
            } else if (mode == 2) {
#pragma unroll
                for (int s = 0; s < SPW; s++) {
                    int nd = (n0 + s) * DD + lane;
                    float yv = g_yz[nd];
                    float acc = C1f * g_kz[0][nd] + C3f * g_kz[2][nd] + C4f * g_kz[3][nd] +
                                C5f * g_kz[4][nd] + C6f * g_kz[5][nd];
                    float y1 = yv + dtc * acc;
                    g_y1z[nd] = y1;
                    xv[s] = y1;
                    xw[s * DD + lane] = y1;
                }
            } else {
                float a0 = A_TAB[st][0], a1 = A_TAB[st][1], a2 = A_TAB[st][2],
                      a3 = A_TAB[st][3], a4 = A_TAB[st][4];
                int nk = NK_TAB[st];
#pragma unroll
                for (int s = 0; s < SPW; s++) {
                    int nd = (n0 + s) * DD + lane;
                    float v = g_yz[nd];
                    float acc = a0 * g_kz[0][nd];
                    if (nk > 1) acc += a1 * g_kz[1][nd];
                    if (nk > 2) acc += a2 * g_kz[2][nd];
                    if (nk > 3) acc += a3 * g_kz[3][nd];
                    if (nk > 4) acc += a4 * g_kz[4][nd];
                    v += dtc * acc;
                    xv[s] = v;
                    xw[s * DD + lane] = v;
                }
            }
            __syncwarp();

            // ---- pass 1 (packed over d-pairs): h1 = W1 @ x + b1, lane owns j = c*32+lane
            unsigned long long h1p[SPW][4];
#pragma unroll
            for (int s = 0; s < SPW; s++)
#pragma unroll
                for (int c = 0; c < 4; c++) h1p[s][c] = pk2(sb1[c * 32 + lane], 0.f);
#pragma unroll
            for (int d0 = 0; d0 < DD; d0 += 4) {
                ulonglong2 xp[SPW];
#pragma unroll
                for (int s = 0; s < SPW; s++) xp[s] = *(const ulonglong2*)&xw[s * DD + d0];
#pragma unroll
                for (int c = 0; c < 4; c++) {
                    ulonglong2 wp = *(const ulonglong2*)&sW1[(c * 32 + lane) * P36 + d0];
#pragma unroll
                    for (int s = 0; s < SPW; s++) {
                        ffma2(h1p[s][c], wp.x, xp[s].x);
                        ffma2(h1p[s][c], wp.y, xp[s].y);
                    }
                }
            }

            // ---- pass 2: pair-lane trick. acc.lo accumulates h2, acc.hi accumulates vv.
            unsigned long long acc2[SPW][4];
#pragma unroll
            for (int s = 0; s < SPW; s++)
#pragma unroll
                for (int c = 0; c < 4; c++) acc2[s][c] = pk2(sb2[c * 32 + lane], 0.f);

#pragma unroll
            for (int half = 0; half < 2; half++) {
                // stage (relu, mask) pairs for this half's 64 i-values
#pragma unroll
                for (int s = 0; s < SPW; s++)
#pragma unroll
                    for (int cc = 0; cc < 2; cc++) {
                        int c = half * 2 + cc;
                        float lo, hi;
                        upk2(h1p[s][c], lo, hi);
                        float v = lo + hi;
                        float r = fmaxf(v, 0.f);
                        float m = (v > 0.f) ? 1.f : 0.f;
                        *(unsigned long long*)&hw[s * HH + 2 * (cc * 32 + lane)] = pk2(r, m);
                    }
                __syncwarp();
#pragma unroll 4
                for (int ii = 0; ii < 64; ii += 4) {
                    int i0 = half * 64 + ii;
                    ulonglong2 ha[SPW], hb[SPW];
#pragma unroll
                    for (int s = 0; s < SPW; s++) {
                        ha[s] = *(const ulonglong2*)&hw[s * HH + 2 * ii];
                        hb[s] = *(const ulonglong2*)&hw[s * HH + 2 * ii + 4];
                    }
#pragma unroll
                    for (int c = 0; c < 4; c++) {
                        const float* wr = &sWM[(c * 32 + lane) * PW + 2 * i0];
                        ulonglong2 wa = *(const ulonglong2*)&wr[0];
                        ulonglong2 wb = *(const ulonglong2*)&wr[4];
#pragma unroll
                        for (int s = 0; s < SPW; s++) {
                            ffma2(acc2[s][c], wa.x, ha[s].x);
                            ffma2(acc2[s][c], wa.y, ha[s].y);
                            ffma2(acc2[s][c], wb.x, hb[s].x);
                            ffma2(acc2[s][c], wb.y, hb[s].y);
                        }
                    }
                }
                __syncwarp();
            }

            // unpack: relu(h2) to staging (plain), dlogp partial
            float dlp[SPW];
#pragma unroll
            for (int s = 0; s < SPW; s++) {
                float a = 0.f;
#pragma unroll
                for (int c = 0; c < 4; c++) {
                    float h2v, vvv;
                    upk2(acc2[s][c], h2v, vvv);
                    hw[s * HH + c * 32 + lane] = fmaxf(h2v, 0.f);
                    if (h2v > 0.f) a += vvv;
                }
                dlp[s] = a;
            }
            __syncwarp();

            // ---- pass 3 (packed over h-pairs): dF = W3 @ relu(h2) + b3, lane owns d = lane
            unsigned long long dFp[SPW];
#pragma unroll
            for (int s = 0; s < SPW; s++) dFp[s] = pk2(sb3[lane], 0.f);
#pragma unroll 8
            for (int h0 = 0; h0 < HH; h0 += 4) {
                ulonglong2 wp = *(const ulonglong2*)&sW3[lane * P132 + h0];
#pragma unroll
                for (int s = 0; s < SPW; s++) {
                    ulonglong2 hp = *(const ulonglong2*)&hw[s * HH + h0];
                    ffma2(dFp[s], wp.x, hp.x);
                    ffma2(dFp[s], wp.y, hp.y);
                }
            }
            __syncwarp();
#pragma unroll
            for (int s = 0; s < SPW; s++) {
                float lo, hi;
                upk2(dFp[s], lo, hi);
                hw[s * HH + lane] = xv[s] - (lo + hi);
            }
            __syncwarp();

            // ---- pass 4 (packed over k-pairs): dz = (x - dF) @ IP - x
            unsigned long long dzp[SPW];
#pragma unroll
            for (int s = 0; s < SPW; s++) dzp[s] = pk2(-xv[s], 0.f);
#pragma unroll
            for (int k0 = 0; k0 < DD; k0 += 4) {
                ulonglong2 ip = *(const ulonglong2*)&sIPT[lane * P36 + k0];
#pragma unroll
                for (int s = 0; s < SPW; s++) {
                    ulonglong2 tp = *(const ulonglong2*)&hw[s * HH + k0];
                    ffma2(dzp[s], ip.x, tp.x);
                    ffma2(dzp[s], ip.y, tp.y);
                }
            }
            float dz[SPW];
#pragma unroll
            for (int s = 0; s < SPW; s++) {
                float lo, hi;
                upk2(dzp[s], lo, hi);
                dz[s] = lo + hi;
            }

            // ---- epilogue
            float dlpAll[SPW];
#pragma unroll
            for (int s = 0; s < SPW; s++) {
                float v = dlp[s];
#pragma unroll
                for (int off = 16; off > 0; off >>= 1) v += __shfl_xor_sync(0xffffffffu, v, off);
                dlpAll[s] = v + trP;
            }

            if (mode != 2) {
#pragma unroll
                for (int s = 0; s < SPW; s++) {
                    int n = n0 + s;
                    g_kz[st][n * DD + lane] = dz[s];
                    if (lane == 0) g_klp[st][n] = dlpAll[s];
                }
            } else {
                float acc = 0.f;
#pragma unroll
                for (int s = 0; s < SPW; s++) {
                    int nd = (n0 + s) * DD + lane;
                    float yv = g_yz[nd];
                    float ev = dtc * (E1f * g_kz[0][nd] + E3f * g_kz[2][nd] + E4f * g_kz[3][nd] +
                                      E5f * g_kz[4][nd] + E6f * g_kz[5][nd] + E7f * dz[s]);
                    float tol = 1e-5f + 1e-5f * fmaxf(fabsf(yv), fabsf(xv[s]));
                    float r = ev / tol;
                    acc += r * r;
                }
                if (lane < SPW) {
                    int s = lane;
                    int n = n0 + s;
                    float k0l = g_klp[0][n], k2l = g_klp[2][n], k3l = g_klp[3][n],
                          k4l = g_klp[4][n], k5l = g_klp[5][n];
                    float ylp = g_ylp[n];
                    float y1lp = ylp + dtc * (C1f * k0l + C3f * k2l + C4f * k3l + C5f * k4l + C6f * k5l);
                    g_y1lp[n] = y1lp;
                    float ev = dtc * (E1f * k0l + E3f * k2l + E4f * k3l + E5f * k4l + E6f * k5l +
                                      E7f * dlpAll[s]);
                    float tol = 1e-5f + 1e-5f * fmaxf(fabsf(ylp), fabsf(y1lp));
                    float r = ev / tol;
                    acc += r * r;
                }
#pragma unroll
                for (int off = 16; off > 0; off >>= 1) acc += __shfl_xor_sync(0xffffffffu, acc, off);
                if (lane == 0) sred[w] = acc;
                __syncthreads();
                if (w == 0) {
                    float v = sred[lane] + sred[lane + 16];
                    v += __shfl_xor_sync(0xffffffffu, v, 8);
                    v += __shfl_xor_sync(0xffffffffu, v, 4);
                    v += __shfl_xor_sync(0xffffffffu, v, 2);
                    v += __shfl_xor_sync(0xffffffffu, v, 1);
                    if (lane == 0) g_partial[step & 1][blockIdx.x] = v;
                }
            }
        }  // stages

        grid_sync();

        // ---- controller (computed identically by every warp of every CTA)
        const float* pp = &g_partial[step & 1][0];
        float v = __ldcg(&pp[lane]) + __ldcg(&pp[lane + 32]) +
                  __ldcg(&pp[lane + 64]) + __ldcg(&pp[lane + 96]);
#pragma unroll
        for (int off = 16; off > 0; off >>= 1) v += __shfl_xor_sync(0xffffffffu, v, off);
        float errn = sqrtf(v / (float)(NN * (DD + 1)));
        int done_cur = done;
        accept = (!done_cur) && (errn <= 1.0f);
        if (accept) t += dtc;
        float factor = (errn > 0.f) ? 0.9f * powf(errn, -0.2f) : 10.0f;
        factor = fminf(fmaxf(factor, 0.2f), 10.0f);
        if (!done_cur) dt = fminf(fmaxf(dtc * factor, 1e-6f), t1);
        done = (t >= t1 - 1e-9f) ? 1 : 0;
        dtc = done ? 0.001f : fminf(dt, t1 - t);
    }  // steps

    // ---- final output with pending accept
#pragma unroll
    for (int s = 0; s < SPW; s++) {
        int nd = (n0 + s) * DD + lane;
        out[nd] = accept ? g_y1z[nd] : g_yz[nd];
    }
}

// ---------------- launch ----------------
extern "C" void kernel_launch(void* const* d_in, const int* in_sizes, int n_in,
                              void* d_out, int out_size) {
    const float* z  = (const float*)d_in[0];
    const float* G  = (const float*)d_in[1];
    const float* W1 = (const float*)d_in[2];
    const float* b1 = (const float*)d_in[3];
    const float* W2 = (const float*)d_in[4];
    const float* b2 = (const float*)d_in[5];
    const float* W3 = (const float*)d_in[6];
    const float* b3 = (const float*)d_in[7];
    const float* T  = (const float*)d_in[8];

    const int smem_floats = HH * P36 + HH * PW + DD * P132 + DD * P36 +
                            2 * HH + DD + 32 + 16 * SPW * DD + 16 * SPW * HH;
    const int smem_bytes = smem_floats * 4;
    cudaFuncSetAttribute(persist_kernel, cudaFuncAttributeMaxDynamicSharedMemorySize, smem_bytes);

    persist_kernel<<<NBLK, TPB, smem_bytes>>>(z, G, W1, b1, W2, b2, W3, b3, T, (float*)d_out);
}

// round 16
// speedup vs baseline: 2.1599x; 1.0208x over previous
#include <cuda_runtime.h>
#include <math.h>
#include <stdint.h>

#define NN 8192
#define DD 32
#define HH 128
#define MMQ 8
#define TPB 256
#define NWARP (TPB / 32)
#define NBLK 128
#define SPW 8
#define P36 36
#define P132 132
#define PW 260   // interleaved (W2, MT) row pitch; 260 % 32 == 4 -> conflict-free
#define NSTEPS 10

// ---------------- device state ----------------
__device__ float g_yz[NN * DD];
__device__ float g_ylp[NN];
__device__ float g_y1z[NN * DD];
__device__ float g_y1lp[NN];
__device__ float g_kz[6][NN * DD];
__device__ float g_klp[6][NN];
__device__ float g_partial[2][NBLK];
__device__ unsigned g_count = 0u;          // self-restoring across replays
__device__ volatile unsigned g_gen = 0u;   // monotonic; barrier compares relatively

// RK45 combine/error coefficients
#define C1f ((float)(35.0 / 384.0))
#define C3f ((float)(500.0 / 1113.0))
#define C4f ((float)(125.0 / 192.0))
#define C5f ((float)(-2187.0 / 6784.0))
#define C6f ((float)(11.0 / 84.0))
#define E1f ((float)(35.0 / 384.0 - 5179.0 / 57600.0))
#define E3f ((float)(500.0 / 1113.0 - 7571.0 / 16695.0))
#define E4f ((float)(125.0 / 192.0 - 393.0 / 640.0))
#define E5f ((float)(-2187.0 / 6784.0 + 92097.0 / 339200.0))
#define E6f ((float)(11.0 / 84.0 - 187.0 / 2100.0))
#define E7f ((float)(-1.0 / 40.0))

__constant__ float A_TAB[7][5] = {
    {0.f, 0.f, 0.f, 0.f, 0.f},
    {0.2f, 0.f, 0.f, 0.f, 0.f},
    {(float)(3.0 / 40.0), (float)(9.0 / 40.0), 0.f, 0.f, 0.f},
    {(float)(44.0 / 45.0), (float)(-56.0 / 15.0), (float)(32.0 / 9.0), 0.f, 0.f},
    {(float)(19372.0 / 6561.0), (float)(-25360.0 / 2187.0), (float)(64448.0 / 6561.0),
     (float)(-212.0 / 729.0), 0.f},
    {(float)(9017.0 / 3168.0), (float)(-355.0 / 33.0), (float)(46732.0 / 5247.0),
     (float)(49.0 / 176.0), (float)(-5103.0 / 18656.0)},
    {0.f, 0.f, 0.f, 0.f, 0.f}};
__constant__ int NK_TAB[7] = {0, 1, 2, 3, 4, 5, 0};

// ---------------- packed f32x2 helpers ----------------
__device__ __forceinline__ void ffma2(unsigned long long& d, unsigned long long a,
                                      unsigned long long b) {
    asm("fma.rn.f32x2 %0, %1, %2, %0;" : "+l"(d) : "l"(a), "l"(b));
}
__device__ __forceinline__ unsigned long long pk2(float lo, float hi) {
    unsigned long long v;
    asm("mov.b64 %0, {%1, %2};" : "=l"(v) : "r"(__float_as_uint(lo)), "r"(__float_as_uint(hi)));
    return v;
}
__device__ __forceinline__ void upk2(unsigned long long v, float& lo, float& hi) {
    unsigned a, b;
    asm("mov.b64 {%0, %1}, %2;" : "=r"(a), "=r"(b) : "l"(v));
    lo = __uint_as_float(a);
    hi = __uint_as_float(b);
}

// ---------------- grid-wide barrier (co-resident grid: 128 CTAs, 1/SM) ----------------
__device__ __forceinline__ void grid_sync() {
    __syncthreads();
    if (threadIdx.x == 0) {
        unsigned old = g_gen;
        __threadfence();
        unsigned a = atomicAdd(&g_count, 1u);
        if (a == (unsigned)(NBLK - 1)) {
            g_count = 0u;
            __threadfence();
            g_gen = old + 1u;
        } else {
            while (g_gen == old) { __nanosleep(64); }
        }
        __threadfence();
    }
    __syncthreads();
}

// ---------------- single persistent kernel: prep + init + integrate ----------------
__global__ __launch_bounds__(TPB, 1) void persist_kernel(
    const float* __restrict__ z, const float* __restrict__ G,
    const float* __restrict__ W1, const float* __restrict__ b1,
    const float* __restrict__ W2, const float* __restrict__ b2,
    const float* __restrict__ W3, const float* __restrict__ b3,
    const float* __restrict__ T, float* __restrict__ out) {
    extern __shared__ float sm[];
    float* sW1 = sm;                        // HH*P36           = 4608
    float* sWM = sW1 + HH * P36;            // HH*PW            = 33280 (W2,MT interleaved)
    float* sW3 = sWM + HH * PW;             // DD*P132          = 4224
    float* sIPT = sW3 + DD * P132;          // DD*P36           = 1152
    float* sb1 = sIPT + DD * P36;           // HH
    float* sb2 = sb1 + HH;                  // HH
    float* sb3 = sb2 + HH;                  // DD
    float* sred = sb3 + DD;                 // 32
    float* xs = sred + 32;                  // NWARP*SPW*DD = 2048
    float* hs = xs + NWARP * SPW * DD;      // NWARP*SPW*HH = 8192

    int tid = threadIdx.x;
    int w = tid >> 5, lane = tid & 31;
    int n0 = (blockIdx.x * NWARP + w) * SPW;
    float* xw = xs + w * (SPW * DD);
    float* hw = hs + w * (SPW * HH);

    // ================= PHASE A: weight staging (W1, W3, biases) =================
    for (int e = tid; e < HH * DD; e += TPB) sW1[(e >> 5) * P36 + (e & 31)] = W1[e];
    for (int e = tid; e < DD * HH; e += TPB) sW3[(e >> 7) * P132 + (e & 127)] = W3[e];
    if (tid < HH) { sb1[tid] = b1[tid]; sb2[tid] = b2[tid]; }
    if (tid < DD) sb3[tid] = b3[tid];

    // ================= PHASE B: prep (redundant per CTA, in shared) =================
    float* sG = xs;            // 8x32
    float* sP = xs + 256;      // 32x32
    float* sC = hs;            // 32x128
    double* Mx = (double*)(hs + 4096);       // 8x16 augmented
    double* Ad = (double*)(hs + 4096 + 256); // 8x8
    float* sAinvG = hs + 4096 + 256 + 128;   // 8x32

    if (tid < MMQ * DD) sG[tid] = G[tid];
    __syncthreads();

    if (tid < MMQ * MMQ) {
        int i = tid >> 3, j = tid & 7;
        double s = 0.0;
        for (int d = 0; d < DD; d++) s += (double)sG[i * DD + d] * (double)sG[j * DD + d];
        Ad[i * MMQ + j] = s;
    }
    __syncthreads();

    {
        int r = tid >> 4, j = tid & 15;
        if (tid < 128) Mx[r * 16 + j] = (j < MMQ) ? Ad[r * MMQ + j] : (((j - MMQ) == r) ? 1.0 : 0.0);
        __syncthreads();
        for (int col = 0; col < MMQ; col++) {
            int piv = col;
            double best = fabs(Mx[col * 16 + col]);
            for (int r2 = col + 1; r2 < MMQ; r2++) {
                double v = fabs(Mx[r2 * 16 + col]);
                if (v > best) { best = v; piv = r2; }
            }
            if (piv != col && tid < 16) {
                double tmp = Mx[col * 16 + tid];
                Mx[col * 16 + tid] = Mx[piv * 16 + tid];
                Mx[piv * 16 + tid] = tmp;
            }
            __syncthreads();
            double invp = 1.0 / Mx[col * 16 + col];
            __syncthreads();
            if (tid < 16) Mx[col * 16 + tid] *= invp;
            __syncthreads();
            double f = 0.0, pcj = 0.0;
            if (tid < 128 && r != col) f = Mx[r * 16 + col];
            if (tid < 128) pcj = Mx[col * 16 + j];
            __syncthreads();
            if (tid < 128 && r != col) Mx[r * 16 + j] -= f * pcj;
            __syncthreads();
        }
    }
    if (tid < MMQ * DD) {
        int m = tid >> 5, d = tid & 31;
        double s = 0.0;
        for (int k = 0; k < MMQ; k++) s += Mx[m * 16 + MMQ + k] * (double)sG[k * DD + d];
        sAinvG[m * DD + d] = (float)s;
    }
    __syncthreads();
    for (int e = tid; e < DD * DD; e += TPB) {
        int a = e >> 5, b = e & 31;
        float s = 0.f;
        for (int m = 0; m < MMQ; m++) s += sG[m * DD + a] * sAinvG[m * DD + b];
        sP[a * DD + b] = s;
        sIPT[b * P36 + a] = ((a == b) ? 1.0f : 0.0f) - s;
    }
    __syncthreads();
    float trP = 0.f;
    for (int a = 0; a < DD; a++) trP += sP[a * DD + a];
    for (int e = tid; e < DD * HH; e += TPB) {
        int a = e >> 7, j = e & 127;
        float s = 0.f;
        for (int b = 0; b < DD; b++)
            s += (((a == b) ? 1.0f : 0.0f) - sP[a * DD + b]) * sW3[b * P132 + j];
        sC[a * HH + j] = s;
    }
    __syncthreads();
    // interleaved weights: sWM[j][2i] = W2[j,i], sWM[j][2i+1] = MT[j,i] = B[i,j]*W2[j,i]
    for (int e = tid; e < HH * HH; e += TPB) {
        int j = e >> 7, i = e & 127;
        float s = 0.f;
        for (int a = 0; a < DD; a++) s += sW1[i * P36 + a] * sC[a * HH + j];
        float w2v = W2[j * HH + i];
        sWM[j * PW + 2 * i] = w2v;
        sWM[j * PW + 2 * i + 1] = s * w2v;
    }

    // ================= PHASE C: init own samples =================
#pragma unroll
    for (int s = 0; s < SPW; s++) {
        int nd = (n0 + s) * DD + lane;
        g_yz[nd] = z[nd];
    }
    if (lane < SPW) g_ylp[n0 + lane] = 0.f;

    float t1 = 2.0f * T[0];
    __syncthreads();  // prep scratch done before main loop reuses hs/xs

    // ================= PHASE D: integrate =================
    float t = 0.f, dt = 0.25f;
    int done = (0.f >= t1 - 1e-9f) ? 1 : 0;
    float dtc = done ? 0.001f : fminf(dt, t1);
    int accept = 0;

    for (int step = 0; step < NSTEPS; step++) {
        for (int st = 0; st < 7; st++) {
            int mode = (st == 0) ? 1 : ((st == 6) ? 2 : 0);

            // ---- stage input x
            float xv[SPW];
            if (mode == 1) {
#pragma unroll
                for (int s = 0; s < SPW; s++) {
                    int nd = (n0 + s) * DD + lane;
                    float v = accept ? g_y1z[nd] : g_yz[nd];
                    if (accept) g_yz[nd] = v;
                    xv[s] = v;
                    xw[s * DD + lane] = v;
                }
                if (lane < SPW && accept) {
                    int n = n0 + lane;
                    g_ylp[n] = g_y1lp[n];
                }
            } else if (mode == 2) {
#pragma unroll
                for (int s = 0; s < SPW; s++) {
                    int nd = (n0 + s) * DD + lane;
                    float yv = g_yz[nd];
                    float acc = C1f * g_kz[0][nd] + C3f * g_kz[2][nd] + C4f * g_kz[3][nd] +
                                C5f * g_kz[4][nd] + C6f * g_kz[5][nd];
                    float y1 = yv + dtc * acc;
                    g_y1z[nd] = y1;
                    xv[s] = y1;
                    xw[s * DD + lane] = y1;
                }
            } else {
                float a0 = A_TAB[st][0], a1 = A_TAB[st][1], a2 = A_TAB[st][2],
                      a3 = A_TAB[st][3], a4 = A_TAB[st][4];
                int nk = NK_TAB[st];
#pragma unroll
                for (int s = 0; s < SPW; s++) {
                    int nd = (n0 + s) * DD + lane;
                    float v = g_yz[nd];
                    float acc = a0 * g_kz[0][nd];
                    if (nk > 1) acc += a1 * g_kz[1][nd];
                    if (nk > 2) acc += a2 * g_kz[2][nd];
                    if (nk > 3) acc += a3 * g_kz[3][nd];
                    if (nk > 4) acc += a4 * g_kz[4][nd];
                    v += dtc * acc;
                    xv[s] = v;
                    xw[s * DD + lane] = v;
                }
            }
            __syncwarp();

            // ---- pass 1 (packed over d-pairs): h1 = W1 @ x + b1, lane owns j = c*32+lane
            unsigned long long h1p[SPW][4];
#pragma unroll
            for (int s = 0; s < SPW; s++)
#pragma unroll
                for (int c = 0; c < 4; c++) h1p[s][c] = pk2(sb1[c * 32 + lane], 0.f);
#pragma unroll
            for (int d0 = 0; d0 < DD; d0 += 4) {
                ulonglong2 xp[SPW];
#pragma unroll
                for (int s = 0; s < SPW; s++) xp[s] = *(const ulonglong2*)&xw[s * DD + d0];
#pragma unroll
                for (int c = 0; c < 4; c++) {
                    ulonglong2 wp = *(const ulonglong2*)&sW1[(c * 32 + lane) * P36 + d0];
#pragma unroll
                    for (int s = 0; s < SPW; s++) {
                        ffma2(h1p[s][c], wp.x, xp[s].x);
                        ffma2(h1p[s][c], wp.y, xp[s].y);
                    }
                }
            }

            // ---- pass 2: pair-lane trick. acc.lo accumulates h2, acc.hi accumulates vv.
            unsigned long long acc2[SPW][4];
#pragma unroll
            for (int s = 0; s < SPW; s++)
#pragma unroll
                for (int c = 0; c < 4; c++) acc2[s][c] = pk2(sb2[c * 32 + lane], 0.f);

#pragma unroll
            for (int half = 0; half < 2; half++) {
                // stage (relu, mask) pairs for this half's 64 i-values
#pragma unroll
                for (int s = 0; s < SPW; s++)
#pragma unroll
                    for (int cc = 0; cc < 2; cc++) {
                        int c = half * 2 + cc;
                        float lo, hi;
                        upk2(h1p[s][c], lo, hi);
                        float v = lo + hi;
                        float r = fmaxf(v, 0.f);
                        float m = (v > 0.f) ? 1.f : 0.f;
                        *(unsigned long long*)&hw[s * HH + 2 * (cc * 32 + lane)] = pk2(r, m);
                    }
                __syncwarp();
#pragma unroll 2
                for (int ii = 0; ii < 64; ii += 4) {
                    int i0 = half * 64 + ii;
                    ulonglong2 ha[SPW], hb[SPW];
#pragma unroll
                    for (int s = 0; s < SPW; s++) {
                        ha[s] = *(const ulonglong2*)&hw[s * HH + 2 * ii];
                        hb[s] = *(const ulonglong2*)&hw[s * HH + 2 * ii + 4];
                    }
#pragma unroll
                    for (int c = 0; c < 4; c++) {
                        const float* wr = &sWM[(c * 32 + lane) * PW + 2 * i0];
                        ulonglong2 wa = *(const ulonglong2*)&wr[0];
                        ulonglong2 wb = *(const ulonglong2*)&wr[4];
#pragma unroll
                        for (int s = 0; s < SPW; s++) {
                            ffma2(acc2[s][c], wa.x, ha[s].x);
                            ffma2(acc2[s][c], wa.y, ha[s].y);
                            ffma2(acc2[s][c], wb.x, hb[s].x);
                            ffma2(acc2[s][c], wb.y, hb[s].y);
                        }
                    }
                }
                __syncwarp();
            }

            // unpack: relu(h2) to staging (plain), dlogp partial
            float dlp[SPW];
#pragma unroll
            for (int s = 0; s < SPW; s++) {
                float a = 0.f;
#pragma unroll
                for (int c = 0; c < 4; c++) {
                    float h2v, vvv;
                    upk2(acc2[s][c], h2v, vvv);
                    hw[s * HH + c * 32 + lane] = fmaxf(h2v, 0.f);
                    if (h2v > 0.f) a += vvv;
                }
                dlp[s] = a;
            }
            __syncwarp();

            // ---- pass 3 (packed over h-pairs): dF = W3 @ relu(h2) + b3, lane owns d = lane
            unsigned long long dFp[SPW];
#pragma unroll
            for (int s = 0; s < SPW; s++) dFp[s] = pk2(sb3[lane], 0.f);
#pragma unroll 8
            for (int h0 = 0; h0 < HH; h0 += 4) {
                ulonglong2 wp = *(const ulonglong2*)&sW3[lane * P132 + h0];
#pragma unroll
                for (int s = 0; s < SPW; s++) {
                    ulonglong2 hp = *(const ulonglong2*)&hw[s * HH + h0];
                    ffma2(dFp[s], wp.x, hp.x);
                    ffma2(dFp[s], wp.y, hp.y);
                }
            }
            __syncwarp();
#pragma unroll
            for (int s = 0; s < SPW; s++) {
                float lo, hi;
                upk2(dFp[s], lo, hi);
                hw[s * HH + lane] = xv[s] - (lo + hi);
            }
            __syncwarp();

            // ---- pass 4 (packed over k-pairs): dz = (x - dF) @ IP - x
            unsigned long long dzp[SPW];
#pragma unroll
            for (int s = 0; s < SPW; s++) dzp[s] = pk2(-xv[s], 0.f);
#pragma unroll
            for (int k0 = 0; k0 < DD; k0 += 4) {
                ulonglong2 ip = *(const ulonglong2*)&sIPT[lane * P36 + k0];
#pragma unroll
                for (int s = 0; s < SPW; s++) {
                    ulonglong2 tp = *(const ulonglong2*)&hw[s * HH + k0];
                    ffma2(dzp[s], ip.x, tp.x);
                    ffma2(dzp[s], ip.y, tp.y);
                }
            }
            float dz[SPW];
#pragma unroll
            for (int s = 0; s < SPW; s++) {
                float lo, hi;
                upk2(dzp[s], lo, hi);
                dz[s] = lo + hi;
            }

            // ---- epilogue
            float dlpAll[SPW];
#pragma unroll
            for (int s = 0; s < SPW; s++) {
                float v = dlp[s];
#pragma unroll
                for (int off = 16; off > 0; off >>= 1) v += __shfl_xor_sync(0xffffffffu, v, off);
                dlpAll[s] = v + trP;
            }

            if (mode != 2) {
#pragma unroll
                for (int s = 0; s < SPW; s++) {
                    int n = n0 + s;
                    g_kz[st][n * DD + lane] = dz[s];
                    if (lane == 0) g_klp[st][n] = dlpAll[s];
                }
            } else {
                float acc = 0.f;
#pragma unroll
                for (int s = 0; s < SPW; s++) {
                    int nd = (n0 + s) * DD + lane;
                    float yv = g_yz[nd];
                    float ev = dtc * (E1f * g_kz[0][nd] + E3f * g_kz[2][nd] + E4f * g_kz[3][nd] +
                                      E5f * g_kz[4][nd] + E6f * g_kz[5][nd] + E7f * dz[s]);
                    float tol = 1e-5f + 1e-5f * fmaxf(fabsf(yv), fabsf(xv[s]));
                    float r = ev / tol;
                    acc += r * r;
                }
                if (lane < SPW) {
                    int s = lane;
                    int n = n0 + s;
                    float k0l = g_klp[0][n], k2l = g_klp[2][n], k3l = g_klp[3][n],
                          k4l = g_klp[4][n], k5l = g_klp[5][n];
                    float ylp = g_ylp[n];
                    float y1lp = ylp + dtc * (C1f * k0l + C3f * k2l + C4f * k3l + C5f * k4l + C6f * k5l);
                    g_y1lp[n] = y1lp;
                    float ev = dtc * (E1f * k0l + E3f * k2l + E4f * k3l + E5f * k4l + E6f * k5l +
                                      E7f * dlpAll[s]);
                    float tol = 1e-5f + 1e-5f * fmaxf(fabsf(ylp), fabsf(y1lp));
                    float r = ev / tol;
                    acc += r * r;
                }
#pragma unroll
                for (int off = 16; off > 0; off >>= 1) acc += __shfl_xor_sync(0xffffffffu, acc, off);
                if (lane == 0) sred[w] = acc;
                __syncthreads();
                if (w == 0) {
                    float v = (lane < NWARP) ? sred[lane] : 0.f;
#pragma unroll
                    for (int off = 16; off > 0; off >>= 1) v += __shfl_xor_sync(0xffffffffu, v, off);
                    if (lane == 0) g_partial[step & 1][blockIdx.x] = v;
                }
            }
        }  // stages

        grid_sync();

        // ---- controller (computed identically by every warp of every CTA)
        const float* pp = &g_partial[step & 1][0];
        float v = __ldcg(&pp[lane]) + __ldcg(&pp[lane + 32]) +
                  __ldcg(&pp[lane + 64]) + __ldcg(&pp[lane + 96]);
#pragma unroll
        for (int off = 16; off > 0; off >>= 1) v += __shfl_xor_sync(0xffffffffu, v, off);
        float errn = sqrtf(v / (float)(NN * (DD + 1)));
        int done_cur = done;
        accept = (!done_cur) && (errn <= 1.0f);
        if (accept) t += dtc;
        float factor = (errn > 0.f) ? 0.9f * powf(errn, -0.2f) : 10.0f;
        factor = fminf(fmaxf(factor, 0.2f), 10.0f);
        if (!done_cur) dt = fminf(fmaxf(dtc * factor, 1e-6f), t1);
        done = (t >= t1 - 1e-9f) ? 1 : 0;
        dtc = done ? 0.001f : fminf(dt, t1 - t);
    }  // steps

    // ---- final output with pending accept
#pragma unroll
    for (int s = 0; s < SPW; s++) {
        int nd = (n0 + s) * DD + lane;
        out[nd] = accept ? g_y1z[nd] : g_yz[nd];
    }
}

// ---------------- launch ----------------
extern "C" void kernel_launch(void* const* d_in, const int* in_sizes, int n_in,
                              void* d_out, int out_size) {
    const float* z  = (const float*)d_in[0];
    const float* G  = (const float*)d_in[1];
    const float* W1 = (const float*)d_in[2];
    const float* b1 = (const float*)d_in[3];
    const float* W2 = (const float*)d_in[4];
    const float* b2 = (const float*)d_in[5];
    const float* W3 = (const float*)d_in[6];
    const float* b3 = (const float*)d_in[7];
    const float* T  = (const float*)d_in[8];

    const int smem_floats = HH * P36 + HH * PW + DD * P132 + DD * P36 +
                            2 * HH + DD + 32 + NWARP * SPW * DD + NWARP * SPW * HH;
    const int smem_bytes = smem_floats * 4;
    cudaFuncSetAttribute(persist_kernel, cudaFuncAttributeMaxDynamicSharedMemorySize, smem_bytes);

    persist_kernel<<<NBLK, TPB, smem_bytes>>>(z, G, W1, b1, W2, b2, W3, b3, T, (float*)d_out);
}